// round 12
// baseline (speedup 1.0000x reference)
#include <cuda_runtime.h>
#include <cuda_fp16.h>
#include <math.h>
#include <stdint.h>

#define NNODES 100000
#define NEDGES 320000
#define NGRAPH 2048
#define HID    256
#define EDIM   128
#define NODE_F 48
#define EDGE_F 6
#define NLAYER 8
#define NBLKD  ((NNODES + 255) / 256)   // 391

// ---------------- scratch (device globals) ----------------------------------
__device__ __half  g_hh0[(size_t)NNODES * HID];
__device__ __half  g_hh1[(size_t)NNODES * HID];
__device__ __half  g_zh [(size_t)NNODES * HID];
__device__ __half  g_aeffh[(size_t)NNODES * HID];
__device__ __half  g_s1h [(size_t)NNODES * EDIM];
__device__ __half2 g_w1p[(size_t)NLAYER * (HID / 2) * HID];
__device__ __half2 g_w2p[(size_t)NLAYER * (HID / 2) * HID];
__device__ __half2 g_w1a[(size_t)(HID / 2) * EDIM];
__device__ float   g_eap[(size_t)NEDGES * 8];
__device__ float   g_stats[2 * HID];
__device__ float   g_gsum[(size_t)NGRAPH * HID];
__device__ float   g_gsq [(size_t)NGRAPH * HID];
__device__ float   g_sc  [NGRAPH];
__device__ float   g_cnt [NGRAPH];
__device__ float   g_wf  [(size_t)NLAYER * 7 * HID];
__device__ int     g_deg [NNODES];
__device__ int     g_bsum[NBLKD];
__device__ int     g_boffs[NBLKD];
__device__ int     g_rowstart[NNODES + 1];
__device__ int     g_cursor[NNODES];
__device__ int     g_csr_eid[NEDGES];
__device__ int     g_csr_src[NEDGES];
__device__ int     g_gstart[NGRAPH + 1];

// ---------------- common helpers ---------------------------------------------
__device__ __forceinline__ uint32_t f2tf32(float x) {
    uint32_t r;
    asm volatile("cvt.rna.tf32.f32 %0, %1;" : "=r"(r) : "f"(x));
    return r;
}
__device__ __forceinline__ void cp16s(uint32_t d, const void* src, bool pred) {
    int sz = pred ? 16 : 0;
    asm volatile("cp.async.cg.shared.global [%0], [%1], 16, %2;" :: "r"(d), "l"(src), "r"(sz));
}
__device__ __forceinline__ void cp_commit() { asm volatile("cp.async.commit_group;"); }
template <int Np>
__device__ __forceinline__ void cp_wait() { asm volatile("cp.async.wait_group %0;" :: "n"(Np)); }
__device__ __forceinline__ void mma_f16(float* c, const uint32_t* a, const uint32_t* b) {
    asm volatile(
        "mma.sync.aligned.m16n8k16.row.col.f32.f16.f16.f32 "
        "{%0,%1,%2,%3}, {%4,%5,%6,%7}, {%8,%9}, {%0,%1,%2,%3};"
        : "+f"(c[0]), "+f"(c[1]), "+f"(c[2]), "+f"(c[3])
        : "r"(a[0]), "r"(a[1]), "r"(a[2]), "r"(a[3]), "r"(b[0]), "r"(b[1]));
}
__device__ __forceinline__ void ldsm4(uint32_t* r, uint32_t addr) {
    asm volatile("ldmatrix.sync.aligned.m8n8.x4.shared.b16 {%0,%1,%2,%3}, [%4];"
                 : "=r"(r[0]), "=r"(r[1]), "=r"(r[2]), "=r"(r[3]) : "r"(addr));
}

extern __shared__ char smemc[];

// ===================== fused MLP + stats ========================================
#define FA_STRIDE 72
#define FA_TILE_BYTES (128 * FA_STRIDE * 2)
#define FB2_STRIDE 260
#define FB_TILE2 (32 * FB2_STRIDE)
#define FTMP_STRIDE 264
#define OFF_B (2 * FA_TILE_BYTES)
#define OFF_TMP (OFF_B + 2 * FB_TILE2 * 4)
#define FUSED_SMEM (OFF_TMP + 128 * FTMP_STRIDE * 2)   // 171008

__global__ __launch_bounds__(512, 1) void fused_mlp(
    int M, const __half* __restrict__ A,
    const __half2* __restrict__ W1p, const __half2* __restrict__ W2p,
    const float* __restrict__ b1, const float* __restrict__ b2,
    const int* __restrict__ batchp,
    float* __restrict__ gsum, float* __restrict__ gsq, float* __restrict__ stats,
    __half* __restrict__ Z)
{
    uint32_t sb = (uint32_t)__cvta_generic_to_shared(smemc);
    const __half2* hB = (const __half2*)(smemc + OFF_B);
    __half* tmp = (__half*)(smemc + OFF_TMP);
    uint32_t sbT = sb + OFF_TMP;

    const int tid = threadIdx.x;
    const int warp = tid >> 5;
    const int lane = tid & 31;
    const int g = lane >> 2;
    const int tq = lane & 3;
    const int m0 = blockIdx.x * 128;
    const int wm = (warp & 3) * 32;
    const int wn = (warp >> 2) * 64;
    const int lrow = ((lane >> 3) & 1) * 8 + (lane & 7);
    const int lcol = (lane >> 4) * 8;

    float acc[2][8][4];
#pragma unroll
    for (int i = 0; i < 2; i++)
#pragma unroll
        for (int j = 0; j < 8; j++)
#pragma unroll
            for (int r = 0; r < 4; r++) acc[i][j][r] = 0.0f;

    auto fillA = [&](int buf, int k0) {
#pragma unroll
        for (int it = 0; it < 2; it++) {
            int chunk = tid + it * 512;
            int r = chunk >> 3, c = (chunk & 7) * 8;
            bool p = (m0 + r) < M;
            cp16s(sb + buf * FA_TILE_BYTES + (r * FA_STRIDE + c) * 2,
                  A + (size_t)(p ? m0 + r : 0) * 256 + k0 + c, p);
        }
    };
    auto fillB = [&](int buf, int k0, const __half2* W) {
#pragma unroll
        for (int it = 0; it < 4; it++) {
            int chunk = tid + it * 512;
            int pr = chunk >> 6, c2 = (chunk & 63) * 4;
            cp16s(sb + OFF_B + (buf * FB_TILE2 + pr * FB2_STRIDE + c2) * 4,
                  W + (size_t)((k0 >> 1) + pr) * 256 + c2, true);
        }
    };

    // phase 1: acc = A @ W1
    fillA(0, 0);
    fillB(0, 0, W1p);
    cp_commit();

    int buf = 0;
#pragma unroll 1
    for (int i = 0; i < 4; i++) {
        if (i < 3) {
            fillA(buf ^ 1, (i + 1) * 64);
            fillB(buf ^ 1, (i + 1) * 64, W1p);
        } else {
            fillB(buf ^ 1, 0, W2p);
        }
        cp_commit();
        cp_wait<1>();
        __syncthreads();

        uint32_t abase = sb + buf * FA_TILE_BYTES;
        const __half2* Bb = hB + buf * FB_TILE2;
#pragma unroll
        for (int kk = 0; kk < 4; kk++) {
            uint32_t af[2][4];
#pragma unroll
            for (int mi = 0; mi < 2; mi++)
                ldsm4(af[mi], abase + ((wm + mi * 16 + lrow) * FA_STRIDE + kk * 16 + lcol) * 2);
            uint32_t bf[8][2];
#pragma unroll
            for (int ni = 0; ni < 8; ni++) {
                const __half2* p = Bb + (kk * 8 + tq) * FB2_STRIDE + wn + ni * 8 + g;
                bf[ni][0] = *(const uint32_t*)(p);
                bf[ni][1] = *(const uint32_t*)(p + 4 * FB2_STRIDE);
            }
#pragma unroll
            for (int mi = 0; mi < 2; mi++)
#pragma unroll
                for (int ni = 0; ni < 8; ni++)
                    mma_f16(acc[mi][ni], af[mi], bf[ni]);
        }
        __syncthreads();
        buf ^= 1;
    }

    if (tid < 128)
        ((int*)smemc)[tid] = (m0 + tid < M) ? __ldg(batchp + m0 + tid) : 0;

    // phase 1 epilogue: tmp = relu(acc + b1)
#pragma unroll
    for (int mi = 0; mi < 2; mi++) {
        int r0 = wm + mi * 16 + g;
        int r1 = r0 + 8;
#pragma unroll
        for (int ni = 0; ni < 8; ni++) {
            int col = wn + ni * 8 + tq * 2;
            float c0 = __ldg(b1 + col);
            float c1 = __ldg(b1 + col + 1);
            float v0 = fmaxf(acc[mi][ni][0] + c0, 0.f);
            float v1 = fmaxf(acc[mi][ni][1] + c1, 0.f);
            float v2 = fmaxf(acc[mi][ni][2] + c0, 0.f);
            float v3 = fmaxf(acc[mi][ni][3] + c1, 0.f);
            *(__half2*)(tmp + r0 * FTMP_STRIDE + col) = __floats2half2_rn(v0, v1);
            *(__half2*)(tmp + r1 * FTMP_STRIDE + col) = __floats2half2_rn(v2, v3);
            acc[mi][ni][0] = 0.f; acc[mi][ni][1] = 0.f;
            acc[mi][ni][2] = 0.f; acc[mi][ni][3] = 0.f;
        }
    }

    // phase 2: acc = tmp @ W2
#pragma unroll 1
    for (int i = 0; i < 4; i++) {
        if (i < 3) {
            fillB(buf ^ 1, (i + 1) * 64, W2p);
            cp_commit();
            cp_wait<1>();
        } else {
            cp_wait<0>();
        }
        __syncthreads();

        const __half2* Bb = hB + buf * FB_TILE2;
#pragma unroll
        for (int kk = 0; kk < 4; kk++) {
            uint32_t af[2][4];
#pragma unroll
            for (int mi = 0; mi < 2; mi++)
                ldsm4(af[mi], sbT + ((wm + mi * 16 + lrow) * FTMP_STRIDE + i * 64 + kk * 16 + lcol) * 2);
            uint32_t bf[8][2];
#pragma unroll
            for (int ni = 0; ni < 8; ni++) {
                const __half2* p = Bb + (kk * 8 + tq) * FB2_STRIDE + wn + ni * 8 + g;
                bf[ni][0] = *(const uint32_t*)(p);
                bf[ni][1] = *(const uint32_t*)(p + 4 * FB2_STRIDE);
            }
#pragma unroll
            for (int mi = 0; mi < 2; mi++)
#pragma unroll
                for (int ni = 0; ni < 8; ni++)
                    mma_f16(acc[mi][ni], af[mi], bf[ni]);
        }
        __syncthreads();
        buf ^= 1;
    }

    // phase 2 epilogue: Z(global) + z(tmp smem)
#pragma unroll
    for (int mi = 0; mi < 2; mi++) {
        int rr0 = wm + mi * 16 + g;
        int rr1 = rr0 + 8;
        int r0 = m0 + rr0;
        int r1 = m0 + rr1;
#pragma unroll
        for (int ni = 0; ni < 8; ni++) {
            int col = wn + ni * 8 + tq * 2;
            float c0 = __ldg(b2 + col);
            float c1 = __ldg(b2 + col + 1);
            __half2 z0 = __floats2half2_rn(acc[mi][ni][0] + c0, acc[mi][ni][1] + c1);
            __half2 z1 = __floats2half2_rn(acc[mi][ni][2] + c0, acc[mi][ni][3] + c1);
            *(__half2*)(tmp + rr0 * FTMP_STRIDE + col) = z0;
            *(__half2*)(tmp + rr1 * FTMP_STRIDE + col) = z1;
            if (r0 < M) *(__half2*)(Z + (size_t)r0 * 256 + col) = z0;
            if (r1 < M) *(__half2*)(Z + (size_t)r1 * 256 + col) = z1;
        }
    }
    __syncthreads();

    // phase 3: per-graph + chip stats from smem z
    {
        const int c = tid & 255;
        const int rbeg = (tid >> 8) * 64;
        const int* sbatch = (const int*)smemc;
        float ts = 0.f, tqs = 0.f;
        int curg = -1;
        float s = 0.f, q = 0.f;
        for (int r = rbeg; r < rbeg + 64; r++) {
            if (m0 + r >= M) break;
            int gg = sbatch[r];
            if (gg != curg) {
                if (curg >= 0) {
                    atomicAdd(gsum + (size_t)curg * 256 + c, s);
                    atomicAdd(gsq + (size_t)curg * 256 + c, q);
                }
                curg = gg; s = 0.f; q = 0.f;
            }
            float v = __half2float(tmp[r * FTMP_STRIDE + c]);
            s += v; q = fmaf(v, v, q);
            ts += v; tqs = fmaf(v, v, tqs);
        }
        if (curg >= 0) {
            atomicAdd(gsum + (size_t)curg * 256 + c, s);
            atomicAdd(gsq + (size_t)curg * 256 + c, q);
        }
        atomicAdd(stats + c, ts);
        atomicAdd(stats + 256 + c, tqs);
    }
}

// ===================== per-graph msq -> m, sc (block per graph) ================
__global__ void graph_msq_kernel(const float* __restrict__ stats,
                                 const float* __restrict__ gamma,
                                 const float* __restrict__ cnt,
                                 float* __restrict__ gsum,
                                 const float* __restrict__ gsq,
                                 float* __restrict__ sc)
{
    __shared__ float red[HID];
    int gb = blockIdx.x;
    int c = threadIdx.x;
    const float invN = 1.0f / (float)NNODES;
    float mu = __ldg(stats + c) * invN;
    float var = __ldg(stats + HID + c) * invN - mu * mu;
    float ac = __ldg(gamma + c) * rsqrtf(var + 1e-5f);
    float cg = cnt[gb];
    size_t gi = (size_t)gb * HID + c;
    float S = gsum[gi], Q = gsq[gi];
    float m = S / cg;
    gsum[gi] = m;
    red[c] = ac * ac * (Q - cg * m * m);
    __syncthreads();
    for (int o = HID / 2; o > 0; o >>= 1) {
        if (c < o) red[c] += red[c + o];
        __syncthreads();
    }
    if (c == 0) sc[gb] = rsqrtf(1e-5f + red[0] / cg);
}

// ===================== node-parallel normalize + ReLU ==========================
__global__ void final_norm_kernel(const __half* __restrict__ zh,
                                  const float* __restrict__ stats,
                                  const float* __restrict__ gamma,
                                  const float* __restrict__ gmean,
                                  const float* __restrict__ sc,
                                  const int* __restrict__ batch,
                                  __half* __restrict__ hout)
{
    int r = blockIdx.x;
    int c = threadIdx.x;
    int g = __ldg(batch + r);
    const float invN = 1.0f / (float)NNODES;
    float mu = __ldg(stats + c) * invN;
    float var = __ldg(stats + HID + c) * invN - mu * mu;
    float acs = __ldg(gamma + c) * rsqrtf(var + 1e-5f) * __ldg(sc + g);
    size_t i = (size_t)r * HID + c;
    float v = acs * (__half2float(zh[i]) - __ldg(gmean + (size_t)g * HID + c));
    hout[i] = __float2half(fmaxf(v, 0.f));
}

// ===================== fp16 GEMM (attention, tanh) =============================
#define HA_STRIDE 72
#define HA_TILE_BYTES (128 * HA_STRIDE * 2)

__global__ __launch_bounds__(256, 2) void hgemm_att(
    int M, const __half* __restrict__ A, const __half2* __restrict__ Bp,
    const float* __restrict__ bias, __half* __restrict__ Ch)
{
    constexpr int WN = 128;
    constexpr int HB2_STRIDE = WN + 4;
    constexpr int HB_TILE2 = 32 * HB2_STRIDE;
    const __half2* hB = (const __half2*)(smemc + 2 * HA_TILE_BYTES);
    uint32_t sb = (uint32_t)__cvta_generic_to_shared(smemc);
    uint32_t sbB = sb + 2 * HA_TILE_BYTES;

    const int tid = threadIdx.x;
    const int warp = tid >> 5;
    const int lane = tid & 31;
    const int g = lane >> 2;
    const int tq = lane & 3;
    const int m0 = blockIdx.y * 128;
    const int wm = (warp >> 1) * 32;
    const int wn = (warp & 1) * 64;
    const int lrow = ((lane >> 3) & 1) * 8 + (lane & 7);
    const int lcol = (lane >> 4) * 8;

    float acc[2][8][4];
#pragma unroll
    for (int i = 0; i < 2; i++)
#pragma unroll
        for (int j = 0; j < 8; j++)
#pragma unroll
            for (int r = 0; r < 4; r++) acc[i][j][r] = 0.0f;

    auto fillA = [&](int buf, int k0) {
#pragma unroll
        for (int it = 0; it < 4; it++) {
            int chunk = tid + it * 256;
            int r = chunk >> 3, c = (chunk & 7) * 8;
            bool p = (m0 + r) < M;
            cp16s(sb + buf * HA_TILE_BYTES + (r * HA_STRIDE + c) * 2,
                  A + (size_t)(p ? m0 + r : 0) * 256 + k0 + c, p);
        }
    };
    auto fillB = [&](int buf, int k0) {
#pragma unroll
        for (int it = 0; it < 4; it++) {
            int chunk = tid + it * 256;
            int pr = chunk >> 5, c2 = (chunk & 31) * 4;
            cp16s(sbB + (buf * HB_TILE2 + pr * HB2_STRIDE + c2) * 4,
                  Bp + (size_t)((k0 >> 1) + pr) * WN + c2, true);
        }
    };

    fillA(0, 0);
    fillB(0, 0);
    cp_commit();

    int buf = 0;
#pragma unroll 1
    for (int i = 0; i < 4; i++) {
        if (i + 1 < 4) {
            fillA(buf ^ 1, (i + 1) * 64);
            fillB(buf ^ 1, (i + 1) * 64);
            cp_commit();
            cp_wait<1>();
        } else {
            cp_wait<0>();
        }
        __syncthreads();

        uint32_t abase = sb + buf * HA_TILE_BYTES;
        const __half2* Bb = hB + buf * HB_TILE2;
#pragma unroll
        for (int kk = 0; kk < 4; kk++) {
            uint32_t af[2][4];
#pragma unroll
            for (int mi = 0; mi < 2; mi++)
                ldsm4(af[mi], abase + ((wm + mi * 16 + lrow) * HA_STRIDE + kk * 16 + lcol) * 2);
            uint32_t bf[8][2];
#pragma unroll
            for (int ni = 0; ni < 8; ni++) {
                const __half2* p = Bb + (kk * 8 + tq) * HB2_STRIDE + wn + ni * 8 + g;
                bf[ni][0] = *(const uint32_t*)(p);
                bf[ni][1] = *(const uint32_t*)(p + 4 * HB2_STRIDE);
            }
#pragma unroll
            for (int mi = 0; mi < 2; mi++)
#pragma unroll
                for (int ni = 0; ni < 8; ni++)
                    mma_f16(acc[mi][ni], af[mi], bf[ni]);
        }
        __syncthreads();
        buf ^= 1;
    }

#pragma unroll
    for (int mi = 0; mi < 2; mi++) {
        int r0 = m0 + wm + mi * 16 + g;
        int r1 = r0 + 8;
#pragma unroll
        for (int ni = 0; ni < 8; ni++) {
            int col = wn + ni * 8 + tq * 2;
            float b0 = __ldg(bias + col);
            float b1 = __ldg(bias + col + 1);
            float v0 = tanhf(acc[mi][ni][0] + b0);
            float v1 = tanhf(acc[mi][ni][1] + b1);
            float v2 = tanhf(acc[mi][ni][2] + b0);
            float v3 = tanhf(acc[mi][ni][3] + b1);
            if (r0 < M) *(__half2*)(Ch + (size_t)r0 * WN + col) = __floats2half2_rn(v0, v1);
            if (r1 < M) *(__half2*)(Ch + (size_t)r1 * WN + col) = __floats2half2_rn(v2, v3);
        }
    }
}

// ---------------- weight packs ---------------------------------------------------
__global__ void wpack_kernel(const float* __restrict__ w1, const float* __restrict__ w2,
                             __half2* __restrict__ w1p, __half2* __restrict__ w2p)
{
    int idx = blockIdx.x * 256 + threadIdx.x;
    int l = idx >> 15;
    int rem = idx & 32767;
    int p = rem >> 8;
    int n = rem & 255;
    size_t base = (size_t)l * 65536 + (size_t)(2 * p) * 256 + n;
    w1p[idx] = __floats2half2_rn(__ldg(w1 + base), __ldg(w1 + base + 256));
    w2p[idx] = __floats2half2_rn(__ldg(w2 + base), __ldg(w2 + base + 256));
}
__global__ void wpack_att_kernel(const float* __restrict__ w, __half2* __restrict__ wp)
{
    int idx = blockIdx.x * 256 + threadIdx.x;
    int p = idx >> 7;
    int n = idx & 127;
    size_t base = (size_t)(2 * p) * 128 + n;
    wp[idx] = __floats2half2_rn(__ldg(w + base), __ldg(w + base + 128));
}

// ===================== mma.sync TF32 GEMM (node embed) ========================
#define GA_STRIDE 36
#define GB_STRIDE 132
#define A_TILE_W (128 * GA_STRIDE)
#define B_TILE_W (32 * GB_STRIDE)
#define GEMM_SMEM_BYTES ((2 * A_TILE_W + 2 * B_TILE_W) * 4)

__device__ __forceinline__ void cp16(float* dst, const float* src, bool pred) {
    cp16s((uint32_t)__cvta_generic_to_shared(dst), src, pred);
}
__device__ __forceinline__ void mma_tf32(float* c, const uint32_t* a, const uint32_t* b) {
    asm volatile(
        "mma.sync.aligned.m16n8k8.row.col.f32.tf32.tf32.f32 "
        "{%0,%1,%2,%3}, {%4,%5,%6,%7}, {%8,%9}, {%0,%1,%2,%3};"
        : "+f"(c[0]), "+f"(c[1]), "+f"(c[2]), "+f"(c[3])
        : "r"(a[0]), "r"(a[1]), "r"(a[2]), "r"(a[3]), "r"(b[0]), "r"(b[1]));
}

__global__ __launch_bounds__(256, 2) void tf32_gemm_h(
    int M, int N, int K,
    const float* __restrict__ A, const float* __restrict__ B,
    const float* __restrict__ bias, __half* __restrict__ Chh)
{
    float* sm = (float*)smemc;
    float* As = sm;
    float* Bs = sm + 2 * A_TILE_W;

    const int tid = threadIdx.x;
    const int warp = tid >> 5;
    const int lane = tid & 31;
    const int g = lane >> 2;
    const int tq = lane & 3;
    const int m0 = blockIdx.y * 128;
    const int n0 = blockIdx.x * 128;
    const int wm = (warp >> 1) * 32;
    const int wn = (warp & 1) * 64;

    float acc[2][8][4];
#pragma unroll
    for (int i = 0; i < 2; i++)
#pragma unroll
        for (int j = 0; j < 8; j++)
#pragma unroll
            for (int r = 0; r < 4; r++) acc[i][j][r] = 0.0f;

    const int arow = tid >> 3;
    const int ac4 = tid & 7;
    const int brow = tid >> 5;
    const int bc4 = tid & 31;
    const int nk = (K + 31) / 32;

    {
#pragma unroll
        for (int it = 0; it < 4; it++) {
            int row = arow + it * 32;
            int gm = m0 + row;
            int gk = ac4 * 4;
            bool p = (gm < M) && (gk < K);
            const float* src = A + (size_t)(p ? gm : 0) * K + (p ? gk : 0);
            cp16(As + row * GA_STRIDE + ac4 * 4, src, p);
        }
#pragma unroll
        for (int it = 0; it < 4; it++) {
            int row = brow + it * 8;
            bool p = (row < K);
            const float* src = B + (size_t)(p ? row : 0) * N + n0 + bc4 * 4;
            cp16(Bs + row * GB_STRIDE + bc4 * 4, src, p);
        }
        cp_commit();
    }

    int buf = 0;
    for (int i = 0; i < nk; i++) {
        if (i + 1 < nk) {
            const int kc = i + 1;
            float* Ad = As + (buf ^ 1) * A_TILE_W;
            float* Bd = Bs + (buf ^ 1) * B_TILE_W;
#pragma unroll
            for (int it = 0; it < 4; it++) {
                int row = arow + it * 32;
                int gm = m0 + row;
                int gk = kc * 32 + ac4 * 4;
                bool p = (gm < M) && (gk < K);
                const float* src = A + (size_t)(p ? gm : 0) * K + (p ? gk : 0);
                cp16(Ad + row * GA_STRIDE + ac4 * 4, src, p);
            }
#pragma unroll
            for (int it = 0; it < 4; it++) {
                int row = brow + it * 8;
                int gk = kc * 32 + row;
                bool p = (gk < K);
                const float* src = B + (size_t)(p ? gk : 0) * N + n0 + bc4 * 4;
                cp16(Bd + row * GB_STRIDE + bc4 * 4, src, p);
            }
            cp_commit();
            cp_wait<1>();
        } else {
            cp_wait<0>();
        }
        __syncthreads();

        const float* Ab = As + buf * A_TILE_W;
        const float* Bb = Bs + buf * B_TILE_W;
#pragma unroll
        for (int kk = 0; kk < 4; kk++) {
            const int k = kk * 8;
            uint32_t af[2][4];
#pragma unroll
            for (int mi = 0; mi < 2; mi++) {
                const float* p = Ab + (wm + mi * 16 + g) * GA_STRIDE + k + tq;
                af[mi][0] = f2tf32(p[0]);
                af[mi][1] = f2tf32(p[8 * GA_STRIDE]);
                af[mi][2] = f2tf32(p[4]);
                af[mi][3] = f2tf32(p[8 * GA_STRIDE + 4]);
            }
            uint32_t bf[8][2];
#pragma unroll
            for (int ni = 0; ni < 8; ni++) {
                const float* p = Bb + (k + tq) * GB_STRIDE + wn + ni * 8 + g;
                bf[ni][0] = f2tf32(p[0]);
                bf[ni][1] = f2tf32(p[4 * GB_STRIDE]);
            }
#pragma unroll
            for (int mi = 0; mi < 2; mi++)
#pragma unroll
                for (int ni = 0; ni < 8; ni++)
                    mma_tf32(acc[mi][ni], af[mi], bf[ni]);
        }
        __syncthreads();
        buf ^= 1;
    }

#pragma unroll
    for (int mi = 0; mi < 2; mi++) {
        int r0 = m0 + wm + mi * 16 + g;
        int r1 = r0 + 8;
#pragma unroll
        for (int ni = 0; ni < 8; ni++) {
            int col = n0 + wn + ni * 8 + tq * 2;
            float b0 = __ldg(bias + col);
            float b1 = __ldg(bias + col + 1);
            if (r0 < M) *(__half2*)(Chh + (size_t)r0 * N + col) =
                __floats2half2_rn(acc[mi][ni][0] + b0, acc[mi][ni][1] + b1);
            if (r1 < M) *(__half2*)(Chh + (size_t)r1 * N + col) =
                __floats2half2_rn(acc[mi][ni][2] + b0, acc[mi][ni][3] + b1);
        }
    }
}

// ---------------- fused edge weights ------------------------------------------
__global__ void wfuse_kernel(const float* __restrict__ edge_w,
                             const float* __restrict__ edge_b,
                             const float* __restrict__ conv_w,
                             const float* __restrict__ conv_b,
                             float* __restrict__ wf)
{
    int layer = blockIdx.x;
    int k = blockIdx.y;
    int c = threadIdx.x;
    const float* cw = conv_w + (size_t)layer * EDIM * HID;
    float s = 0.f;
    if (k < EDGE_F) {
        for (int j = 0; j < EDIM; j++)
            s = fmaf(__ldg(edge_w + k * EDIM + j), __ldg(cw + (size_t)j * HID + c), s);
    } else {
        for (int j = 0; j < EDIM; j++)
            s = fmaf(__ldg(edge_b + j), __ldg(cw + (size_t)j * HID + c), s);
        s += __ldg(conv_b + (size_t)layer * HID + c);
    }
    wf[((size_t)layer * 7 + k) * HID + c] = s;
}

// ---------------- CSR build (parallel scan) -------------------------------------
__global__ void deg_kernel(const int* __restrict__ dst, int* __restrict__ deg)
{
    int e = blockIdx.x * blockDim.x + threadIdx.x;
    if (e < NEDGES) atomicAdd(&deg[__ldg(dst + e)], 1);
}

__global__ void deg_bsum_kernel(const int* __restrict__ deg, int* __restrict__ bsum)
{
    __shared__ int sh[256];
    int i = blockIdx.x * 256 + threadIdx.x;
    sh[threadIdx.x] = (i < NNODES) ? deg[i] : 0;
    __syncthreads();
    for (int o = 128; o > 0; o >>= 1) {
        if (threadIdx.x < o) sh[threadIdx.x] += sh[threadIdx.x + o];
        __syncthreads();
    }
    if (threadIdx.x == 0) bsum[blockIdx.x] = sh[0];
}

__global__ void bscan_kernel(const int* __restrict__ bsum, int* __restrict__ boffs)
{
    __shared__ int sh[512];
    int t = threadIdx.x;
    int mine = (t < NBLKD) ? bsum[t] : 0;
    sh[t] = mine;
    __syncthreads();
    for (int o = 1; o < 512; o <<= 1) {
        int v = (t >= o) ? sh[t - o] : 0;
        __syncthreads();
        sh[t] += v;
        __syncthreads();
    }
    if (t < NBLKD) boffs[t] = sh[t] - mine;
}

__global__ void rowfill_kernel(const int* __restrict__ deg, const int* __restrict__ boffs,
                               int* __restrict__ rowstart, int* __restrict__ cursor)
{
    __shared__ int sh[256];
    int b = blockIdx.x, t = threadIdx.x;
    int i = b * 256 + t;
    int d = (i < NNODES) ? deg[i] : 0;
    sh[t] = d;
    __syncthreads();
    for (int o = 1; o < 256; o <<= 1) {
        int v = (t >= o) ? sh[t - o] : 0;
        __syncthreads();
        sh[t] += v;
        __syncthreads();
    }
    if (i < NNODES) {
        int rs = boffs[b] + sh[t] - d;
        rowstart[i] = rs;
        cursor[i] = rs;
    }
    if (i == NNODES - 1) rowstart[NNODES] = NEDGES;
}

__global__ void csr_fill_kernel(const int* __restrict__ src,
                                const int* __restrict__ dst,
                                int* __restrict__ cursor,
                                int* __restrict__ csr_eid,
                                int* __restrict__ csr_src)
{
    int e = blockIdx.x * blockDim.x + threadIdx.x;
    if (e >= NEDGES) return;
    int d = __ldg(dst + e);
    int p = atomicAdd(&cursor[d], 1);
    csr_eid[p] = e;
    csr_src[p] = __ldg(src + e);
}

// ---------------- permute edge attrs into CSR order ----------------------------
__global__ void eaperm_kernel(const float* __restrict__ ea,
                              const int* __restrict__ csr_eid,
                              float* __restrict__ eap)
{
    int j = blockIdx.x * blockDim.x + threadIdx.x;
    if (j >= NEDGES) return;
    int eid = __ldg(csr_eid + j);
    const float* e = ea + (size_t)eid * EDGE_F;
    float4 a = make_float4(__ldg(e), __ldg(e + 1), __ldg(e + 2), __ldg(e + 3));
    float2 b = make_float2(__ldg(e + 4), __ldg(e + 5));
    *(float4*)(eap + (size_t)j * 8) = a;
    *(float2*)(eap + (size_t)j * 8 + 4) = b;
}

// ---------------- graph ranges --------------------------------------------------
__global__ void gstart_min_kernel(const int* __restrict__ batch, int* __restrict__ gstart)
{
    int n = blockIdx.x * blockDim.x + threadIdx.x;
    if (n < NNODES) atomicMin(&gstart[__ldg(batch + n)], n);
}

__global__ void gstart_fix_kernel(int* __restrict__ gstart, float* __restrict__ cnt)
{
    __shared__ int sg[NGRAPH + 1];
    int t = threadIdx.x;
    for (int i = t; i <= NGRAPH; i += 1024) sg[i] = gstart[i];
    __syncthreads();
    if (t == 0) {
        sg[NGRAPH] = NNODES;
        for (int g2 = NGRAPH - 1; g2 >= 0; g2--)
            if (sg[g2] > sg[g2 + 1]) sg[g2] = sg[g2 + 1];
    }
    __syncthreads();
    for (int i = t; i <= NGRAPH; i += 1024) gstart[i] = sg[i];
    for (int i = t; i < NGRAPH; i += 1024)
        cnt[i] = fmaxf((float)(sg[i + 1] - sg[i]), 1.0f);
}

// ---------------- GINE gather v4: dual-edge ILP --------------------------------
__device__ __forceinline__ float4 h4load(const uint2* hp, int idx) {
    uint2 u = __ldg(hp + idx);
    float2 f0 = __half22float2(*(__half2*)&u.x);
    float2 f1 = __half22float2(*(__half2*)&u.y);
    return make_float4(f0.x, f0.y, f1.x, f1.y);
}

__device__ __forceinline__ void edge_acc(float4& a, const float4& hv,
                                         const float4& e03, const float2& e45,
                                         const float4* w, const float4& bf)
{
    float4 ee = bf;
    ee.x = fmaf(e03.x, w[0].x, ee.x); ee.y = fmaf(e03.x, w[0].y, ee.y);
    ee.z = fmaf(e03.x, w[0].z, ee.z); ee.w = fmaf(e03.x, w[0].w, ee.w);
    ee.x = fmaf(e03.y, w[1].x, ee.x); ee.y = fmaf(e03.y, w[1].y, ee.y);
    ee.z = fmaf(e03.y, w[1].z, ee.z); ee.w = fmaf(e03.y, w[1].w, ee.w);
    ee.x = fmaf(e03.z, w[2].x, ee.x); ee.y = fmaf(e03.z, w[2].y, ee.y);
    ee.z = fmaf(e03.z, w[2].z, ee.z); ee.w = fmaf(e03.z, w[2].w, ee.w);
    ee.x = fmaf(e03.w, w[3].x, ee.x); ee.y = fmaf(e03.w, w[3].y, ee.y);
    ee.z = fmaf(e03.w, w[3].z, ee.z); ee.w = fmaf(e03.w, w[3].w, ee.w);
    ee.x = fmaf(e45.x, w[4].x, ee.x); ee.y = fmaf(e45.x, w[4].y, ee.y);
    ee.z = fmaf(e45.x, w[4].z, ee.z); ee.w = fmaf(e45.x, w[4].w, ee.w);
    ee.x = fmaf(e45.y, w[5].x, ee.x); ee.y = fmaf(e45.y, w[5].y, ee.y);
    ee.z = fmaf(e45.y, w[5].z, ee.z); ee.w = fmaf(e45.y, w[5].w, ee.w);
    a.x += fmaxf(hv.x + ee.x, 0.f);
    a.y += fmaxf(hv.y + ee.y, 0.f);
    a.z += fmaxf(hv.z + ee.z, 0.f);
    a.w += fmaxf(hv.w + ee.w, 0.f);
}

__global__ __launch_bounds__(256) void gine_gather_fused(
    const __half* __restrict__ h,
    const float* __restrict__ eap,
    const int* __restrict__ rowstart,
    const int* __restrict__ csr_src,
    const float* __restrict__ wf,
    const float* __restrict__ eps_ptr,
    __half* __restrict__ aeffh,
    float* __restrict__ stats,
    float* __restrict__ gsum,
    float* __restrict__ gsq)
{
    {
        int gid = blockIdx.x * 256 + threadIdx.x;
        if (gid < 262144) {
            gsum[gid] = 0.f; gsum[gid + 262144] = 0.f;
            gsq[gid] = 0.f;  gsq[gid + 262144] = 0.f;
        }
        if (blockIdx.x == 0) {
            stats[threadIdx.x] = 0.f;
            stats[256 + threadIdx.x] = 0.f;
        }
    }

    const int t = threadIdx.x & 63;
    const int group = (blockIdx.x * blockDim.x + threadIdx.x) >> 6;
    const int ngroups = (gridDim.x * blockDim.x) >> 6;
    const float alpha = 1.0f + __ldg(eps_ptr);

    float4 w[EDGE_F];
#pragma unroll
    for (int k = 0; k < EDGE_F; k++)
        w[k] = __ldg((const float4*)(wf + k * HID) + t);
    float4 bf = __ldg((const float4*)(wf + EDGE_F * HID) + t);

    for (int n = group; n < NNODES; n += ngroups) {
        float4 a = h4load((const uint2*)(h + (size_t)n * HID), t);
        a.x *= alpha; a.y *= alpha; a.z *= alpha; a.w *= alpha;
        float4 a2 = make_float4(0.f, 0.f, 0.f, 0.f);

        int lo = __ldg(rowstart + n), hi = __ldg(rowstart + n + 1);
        int j = lo;
        for (; j + 2 <= hi; j += 2) {
            int s0 = __ldg(csr_src + j);
            int s1 = __ldg(csr_src + j + 1);
            float4 e03a = __ldg((const float4*)(eap + (size_t)j * 8));
            float2 e45a = __ldg((const float2*)(eap + (size_t)j * 8 + 4));
            float4 e03b = __ldg((const float4*)(eap + (size_t)(j + 1) * 8));
            float2 e45b = __ldg((const float2*)(eap + (size_t)(j + 1) * 8 + 4));
            float4 hv0 = h4load((const uint2*)(h + (size_t)s0 * HID), t);
            float4 hv1 = h4load((const uint2*)(h + (size_t)s1 * HID), t);
            edge_acc(a, hv0, e03a, e45a, w, bf);
            edge_acc(a2, hv1, e03b, e45b, w, bf);
        }
        if (j < hi) {
            int s0 = __ldg(csr_src + j);
            float4 e03a = __ldg((const float4*)(eap + (size_t)j * 8));
            float2 e45a = __ldg((const float2*)(eap + (size_t)j * 8 + 4));
            float4 hv0 = h4load((const uint2*)(h + (size_t)s0 * HID), t);
            edge_acc(a, hv0, e03a, e45a, w, bf);
        }
        a.x += a2.x; a.y += a2.y; a.z += a2.z; a.w += a2.w;

        __half2* ap = (__half2*)(aeffh + (size_t)n * HID);
        ap[2 * t]     = __floats2half2_rn(a.x, a.y);
        ap[2 * t + 1] = __floats2half2_rn(a.z, a.w);
    }
}

// ---------------- merged attention + pooling (block per graph) -----------------
__global__ void pool_att_kernel(const __half* __restrict__ h,
                                const __half* __restrict__ s1,
                                const float* __restrict__ w2,
                                const float* __restrict__ b2,
                                const int* __restrict__ gstart,
                                const float* __restrict__ cnt,
                                float* __restrict__ out)
{
    __shared__ float swexp[128];
    __shared__ float sw2[128];
    __shared__ float swsum;
    int g = blockIdx.x;
    int t = threadIdx.x;
    int warp = t >> 5, lane = t & 31;
    if (t < 128) sw2[t] = __ldg(w2 + t);
    if (t == 0) swsum = 0.f;
    float b2v = __ldg(b2);
    int lo = gstart[g], hi = gstart[g + 1];
    float s = 0.f, mx = 0.f, att = 0.f;
    __syncthreads();

    for (int c0 = lo; c0 < hi; c0 += 128) {
        int nchunk = min(128, hi - c0);
        for (int j = warp; j < nchunk; j += 8) {
            const __half2* sp = (const __half2*)(s1 + (size_t)(c0 + j) * EDIM);
            float acc = 0.f;
#pragma unroll
            for (int k = lane; k < 64; k += 32) {
                float2 f = __half22float2(__ldg(sp + k));
                acc = fmaf(f.x, sw2[2 * k], acc);
                acc = fmaf(f.y, sw2[2 * k + 1], acc);
            }
#pragma unroll
            for (int o = 16; o > 0; o >>= 1) acc += __shfl_down_sync(0xffffffffu, acc, o);
            if (lane == 0) swexp[j] = expf(acc + b2v);
        }
        __syncthreads();
        if (t < 32) {
            float wv = 0.f;
            for (int j = t; j < nchunk; j += 32) wv += swexp[j];
#pragma unroll
            for (int o = 16; o > 0; o >>= 1) wv += __shfl_down_sync(0xffffffffu, wv, o);
            if (t == 0) swsum += wv;
        }
        for (int j = 0; j < nchunk; j++) {
            float v = __half2float(__ldg(h + (size_t)(c0 + j) * HID + t));
            s += v;
            mx = fmaxf(mx, v);
            att = fmaf(v, swexp[j], att);
        }
        __syncthreads();
    }
    float* og = out + (size_t)g * (3 * HID);
    og[t] = s / cnt[g];
    og[HID + t] = mx;
    og[2 * HID + t] = att / (swsum + 1e-8f);
}

// ---------------- host launch --------------------------------------------------------
extern "C" void kernel_launch(void* const* d_in, const int* in_sizes, int n_in,
                              void* d_out, int out_size)
{
    const float* x         = (const float*)d_in[0];
    const float* edge_attr = (const float*)d_in[1];
    const float* node_w    = (const float*)d_in[2];
    const float* node_b    = (const float*)d_in[3];
    const float* edge_w    = (const float*)d_in[4];
    const float* edge_b    = (const float*)d_in[5];
    const float* conv_w    = (const float*)d_in[6];
    const float* conv_b    = (const float*)d_in[7];
    const float* mlp_w1    = (const float*)d_in[8];
    const float* mlp_b1    = (const float*)d_in[9];
    const float* mlp_w2    = (const float*)d_in[10];
    const float* mlp_b2    = (const float*)d_in[11];
    const float* eps       = (const float*)d_in[12];
    const float* bn_gamma  = (const float*)d_in[13];
    const float* bn_beta   = (const float*)d_in[14];
    const float* att_w1    = (const float*)d_in[15];
    const float* att_b1    = (const float*)d_in[16];
    const float* att_w2    = (const float*)d_in[17];
    const float* att_b2    = (const float*)d_in[18];
    const int*   edge_index= (const int*)d_in[19];
    const int*   batch     = (const int*)d_in[20];
    float* out = (float*)d_out;
    (void)bn_beta;   // cancels exactly under PairNorm centering

    const int* src = edge_index;
    const int* dst = edge_index + NEDGES;

    const int HG_SMEM_128 = 2 * HA_TILE_BYTES + 2 * 32 * (128 + 4) * 4;

    cudaFuncSetAttribute(tf32_gemm_h, cudaFuncAttributeMaxDynamicSharedMemorySize, GEMM_SMEM_BYTES);
    cudaFuncSetAttribute(fused_mlp, cudaFuncAttributeMaxDynamicSharedMemorySize, FUSED_SMEM);
    cudaFuncSetAttribute(hgemm_att, cudaFuncAttributeMaxDynamicSharedMemorySize, HG_SMEM_128);

    float *p_stats, *p_gsum, *p_gsq, *p_sc, *p_cnt, *p_wf, *p_eap;
    __half *p_hh0, *p_hh1, *p_zh, *p_aeffh, *p_s1h;
    __half2 *p_w1p, *p_w2p, *p_w1a;
    int *p_deg, *p_bsum, *p_boffs, *p_rowstart, *p_cursor, *p_eid, *p_csrc, *p_gstart;
    cudaGetSymbolAddress((void**)&p_hh0, g_hh0);
    cudaGetSymbolAddress((void**)&p_hh1, g_hh1);
    cudaGetSymbolAddress((void**)&p_zh, g_zh);
    cudaGetSymbolAddress((void**)&p_aeffh, g_aeffh);
    cudaGetSymbolAddress((void**)&p_s1h, g_s1h);
    cudaGetSymbolAddress((void**)&p_w1p, g_w1p);
    cudaGetSymbolAddress((void**)&p_w2p, g_w2p);
    cudaGetSymbolAddress((void**)&p_w1a, g_w1a);
    cudaGetSymbolAddress((void**)&p_eap, g_eap);
    cudaGetSymbolAddress((void**)&p_stats, g_stats);
    cudaGetSymbolAddress((void**)&p_gsum, g_gsum);
    cudaGetSymbolAddress((void**)&p_gsq, g_gsq);
    cudaGetSymbolAddress((void**)&p_sc, g_sc);
    cudaGetSymbolAddress((void**)&p_cnt, g_cnt);
    cudaGetSymbolAddress((void**)&p_wf, g_wf);
    cudaGetSymbolAddress((void**)&p_deg, g_deg);
    cudaGetSymbolAddress((void**)&p_bsum, g_bsum);
    cudaGetSymbolAddress((void**)&p_boffs, g_boffs);
    cudaGetSymbolAddress((void**)&p_rowstart, g_rowstart);
    cudaGetSymbolAddress((void**)&p_cursor, g_cursor);
    cudaGetSymbolAddress((void**)&p_eid, g_csr_eid);
    cudaGetSymbolAddress((void**)&p_csrc, g_csr_src);
    cudaGetSymbolAddress((void**)&p_gstart, g_gstart);

    // ----- CSR build (parallel scan)
    cudaMemsetAsync(p_deg, 0, NNODES * sizeof(int));
    deg_kernel<<<(NEDGES + 255) / 256, 256>>>(dst, p_deg);
    deg_bsum_kernel<<<NBLKD, 256>>>(p_deg, p_bsum);
    bscan_kernel<<<1, 512>>>(p_bsum, p_boffs);
    rowfill_kernel<<<NBLKD, 256>>>(p_deg, p_boffs, p_rowstart, p_cursor);
    csr_fill_kernel<<<(NEDGES + 255) / 256, 256>>>(src, dst, p_cursor, p_eid, p_csrc);
    eaperm_kernel<<<(NEDGES + 255) / 256, 256>>>(edge_attr, p_eid, p_eap);

    // ----- graph ranges + counts
    cudaMemsetAsync(p_gstart, 0x7F, (NGRAPH + 1) * sizeof(int));
    gstart_min_kernel<<<(NNODES + 255) / 256, 256>>>(batch, p_gstart);
    gstart_fix_kernel<<<1, 1024>>>(p_gstart, p_cnt);

    // ----- weight prep
    wfuse_kernel<<<dim3(NLAYER, 7), HID>>>(edge_w, edge_b, conv_w, conv_b, p_wf);
    wpack_kernel<<<(NLAYER * 128 * 256) / 256, 256>>>(mlp_w1, mlp_w2, p_w1p, p_w2p);
    wpack_att_kernel<<<(128 * 128) / 256, 256>>>(att_w1, p_w1a);

    // ----- node embedding (tf32, half output)
    {
        dim3 grid(HID / 128, (NNODES + 127) / 128);
        tf32_gemm_h<<<grid, 256, GEMM_SMEM_BYTES>>>(NNODES, HID, NODE_F, x, node_w,
                                                    node_b, p_hh0);
    }

    __half* h_cur = p_hh0;
    __half* h_nxt = p_hh1;
    const int mgrid = (NNODES + 127) / 128;

    for (int i = 0; i < NLAYER; i++) {
        gine_gather_fused<<<2048, 256>>>(
            h_cur, p_eap, p_rowstart, p_csrc,
            p_wf + (size_t)i * 7 * HID, eps + i, p_aeffh, p_stats, p_gsum, p_gsq);

        fused_mlp<<<mgrid, 512, FUSED_SMEM>>>(
            NNODES, p_aeffh,
            p_w1p + (size_t)i * 32768, p_w2p + (size_t)i * 32768,
            mlp_b1 + (size_t)i * HID, mlp_b2 + (size_t)i * HID,
            batch, p_gsum, p_gsq, p_stats, p_zh);

        graph_msq_kernel<<<NGRAPH, HID>>>(p_stats, bn_gamma + (size_t)i * HID,
                                          p_cnt, p_gsum, p_gsq, p_sc);
        final_norm_kernel<<<NNODES, HID>>>(p_zh, p_stats, bn_gamma + (size_t)i * HID,
                                           p_gsum, p_sc, batch, h_nxt);

        __half* t = h_cur; h_cur = h_nxt; h_nxt = t;
    }

    // attention hidden: s1 = tanh(h @ att_w1 + att_b1)
    {
        dim3 agrid(1, (NNODES + 127) / 128);
        hgemm_att<<<agrid, 256, HG_SMEM_128>>>(NNODES, h_cur, p_w1a, att_b1, p_s1h);
    }

    // merged attention-score + pooling
    pool_att_kernel<<<NGRAPH, HID>>>(h_cur, p_s1h, att_w2, att_b2, p_gstart, p_cnt, out);

    (void)in_sizes; (void)n_in; (void)out_size;
}

// round 13
// speedup vs baseline: 1.1638x; 1.1638x over previous
#include <cuda_runtime.h>
#include <cuda_fp16.h>
#include <math.h>
#include <stdint.h>

#define NNODES 100000
#define NEDGES 320000
#define NGRAPH 2048
#define HID    256
#define EDIM   128
#define NODE_F 48
#define EDGE_F 6
#define NLAYER 8
#define NBLKD  ((NNODES + 255) / 256)   // 391

// ---------------- scratch (device globals) ----------------------------------
__device__ __half  g_hh0[(size_t)NNODES * HID];
__device__ __half  g_hh1[(size_t)NNODES * HID];
__device__ __half  g_zh [(size_t)NNODES * HID];
__device__ __half  g_aeffh[(size_t)NNODES * HID];
__device__ __half  g_s1h [(size_t)NNODES * EDIM];
__device__ __half2 g_w1p[(size_t)NLAYER * (HID / 2) * HID];
__device__ __half2 g_w2p[(size_t)NLAYER * (HID / 2) * HID];
__device__ __half2 g_w1a[(size_t)(HID / 2) * EDIM];
__device__ float   g_eap[(size_t)NEDGES * 8];     // CSR-permuted edge attrs (padded)
__device__ float   g_stats[2 * HID];
__device__ float   g_gsum[(size_t)NGRAPH * HID];
__device__ float   g_gsq [(size_t)NGRAPH * HID];
__device__ float   g_cnt [NGRAPH];
__device__ float   g_wf  [(size_t)NLAYER * 7 * HID];
__device__ int     g_deg [NNODES];
__device__ int     g_bsum[NBLKD];
__device__ int     g_boffs[NBLKD];
__device__ int     g_rowstart[NNODES + 1];
__device__ int     g_cursor[NNODES];
__device__ int     g_csr_eid[NEDGES];
__device__ int     g_csr_src[NEDGES];
__device__ int     g_gstart[NGRAPH + 1];

// ---------------- common helpers ---------------------------------------------
__device__ __forceinline__ uint32_t f2tf32(float x) {
    uint32_t r;
    asm volatile("cvt.rna.tf32.f32 %0, %1;" : "=r"(r) : "f"(x));
    return r;
}
__device__ __forceinline__ void cp16s(uint32_t d, const void* src, bool pred) {
    int sz = pred ? 16 : 0;
    asm volatile("cp.async.cg.shared.global [%0], [%1], 16, %2;" :: "r"(d), "l"(src), "r"(sz));
}
__device__ __forceinline__ void cp_commit() { asm volatile("cp.async.commit_group;"); }
template <int Np>
__device__ __forceinline__ void cp_wait() { asm volatile("cp.async.wait_group %0;" :: "n"(Np)); }
__device__ __forceinline__ void mma_f16(float* c, const uint32_t* a, const uint32_t* b) {
    asm volatile(
        "mma.sync.aligned.m16n8k16.row.col.f32.f16.f16.f32 "
        "{%0,%1,%2,%3}, {%4,%5,%6,%7}, {%8,%9}, {%0,%1,%2,%3};"
        : "+f"(c[0]), "+f"(c[1]), "+f"(c[2]), "+f"(c[3])
        : "r"(a[0]), "r"(a[1]), "r"(a[2]), "r"(a[3]), "r"(b[0]), "r"(b[1]));
}
__device__ __forceinline__ void ldsm4(uint32_t* r, uint32_t addr) {
    asm volatile("ldmatrix.sync.aligned.m8n8.x4.shared.b16 {%0,%1,%2,%3}, [%4];"
                 : "=r"(r[0]), "=r"(r[1]), "=r"(r[2]), "=r"(r[3]) : "r"(addr));
}

extern __shared__ char smemc[];

// ===================== fused MLP + stats ========================================
#define FA_STRIDE 72
#define FA_TILE_BYTES (128 * FA_STRIDE * 2)
#define FB2_STRIDE 260
#define FB_TILE2 (32 * FB2_STRIDE)
#define FTMP_STRIDE 264
#define OFF_B (2 * FA_TILE_BYTES)
#define OFF_TMP (OFF_B + 2 * FB_TILE2 * 4)
#define FUSED_SMEM (OFF_TMP + 128 * FTMP_STRIDE * 2)   // 171008

__global__ __launch_bounds__(512, 1) void fused_mlp(
    int M, const __half* __restrict__ A,
    const __half2* __restrict__ W1p, const __half2* __restrict__ W2p,
    const float* __restrict__ b1, const float* __restrict__ b2,
    const int* __restrict__ batchp,
    float* __restrict__ gsum, float* __restrict__ gsq, float* __restrict__ stats,
    __half* __restrict__ Z)
{
    uint32_t sb = (uint32_t)__cvta_generic_to_shared(smemc);
    const __half2* hB = (const __half2*)(smemc + OFF_B);
    __half* tmp = (__half*)(smemc + OFF_TMP);
    uint32_t sbT = sb + OFF_TMP;

    const int tid = threadIdx.x;
    const int warp = tid >> 5;
    const int lane = tid & 31;
    const int g = lane >> 2;
    const int tq = lane & 3;
    const int m0 = blockIdx.x * 128;
    const int wm = (warp & 3) * 32;
    const int wn = (warp >> 2) * 64;
    const int lrow = ((lane >> 3) & 1) * 8 + (lane & 7);
    const int lcol = (lane >> 4) * 8;

    float acc[2][8][4];
#pragma unroll
    for (int i = 0; i < 2; i++)
#pragma unroll
        for (int j = 0; j < 8; j++)
#pragma unroll
            for (int r = 0; r < 4; r++) acc[i][j][r] = 0.0f;

    auto fillA = [&](int buf, int k0) {
#pragma unroll
        for (int it = 0; it < 2; it++) {
            int chunk = tid + it * 512;
            int r = chunk >> 3, c = (chunk & 7) * 8;
            bool p = (m0 + r) < M;
            cp16s(sb + buf * FA_TILE_BYTES + (r * FA_STRIDE + c) * 2,
                  A + (size_t)(p ? m0 + r : 0) * 256 + k0 + c, p);
        }
    };
    auto fillB = [&](int buf, int k0, const __half2* W) {
#pragma unroll
        for (int it = 0; it < 4; it++) {
            int chunk = tid + it * 512;
            int pr = chunk >> 6, c2 = (chunk & 63) * 4;
            cp16s(sb + OFF_B + (buf * FB_TILE2 + pr * FB2_STRIDE + c2) * 4,
                  W + (size_t)((k0 >> 1) + pr) * 256 + c2, true);
        }
    };

    // phase 1: acc = A @ W1
    fillA(0, 0);
    fillB(0, 0, W1p);
    cp_commit();

    int buf = 0;
#pragma unroll 1
    for (int i = 0; i < 4; i++) {
        if (i < 3) {
            fillA(buf ^ 1, (i + 1) * 64);
            fillB(buf ^ 1, (i + 1) * 64, W1p);
        } else {
            fillB(buf ^ 1, 0, W2p);
        }
        cp_commit();
        cp_wait<1>();
        __syncthreads();

        uint32_t abase = sb + buf * FA_TILE_BYTES;
        const __half2* Bb = hB + buf * FB_TILE2;
#pragma unroll
        for (int kk = 0; kk < 4; kk++) {
            uint32_t af[2][4];
#pragma unroll
            for (int mi = 0; mi < 2; mi++)
                ldsm4(af[mi], abase + ((wm + mi * 16 + lrow) * FA_STRIDE + kk * 16 + lcol) * 2);
            uint32_t bf[8][2];
#pragma unroll
            for (int ni = 0; ni < 8; ni++) {
                const __half2* p = Bb + (kk * 8 + tq) * FB2_STRIDE + wn + ni * 8 + g;
                bf[ni][0] = *(const uint32_t*)(p);
                bf[ni][1] = *(const uint32_t*)(p + 4 * FB2_STRIDE);
            }
#pragma unroll
            for (int mi = 0; mi < 2; mi++)
#pragma unroll
                for (int ni = 0; ni < 8; ni++)
                    mma_f16(acc[mi][ni], af[mi], bf[ni]);
        }
        __syncthreads();
        buf ^= 1;
    }

    if (tid < 128)
        ((int*)smemc)[tid] = (m0 + tid < M) ? __ldg(batchp + m0 + tid) : 0;

    // phase 1 epilogue: tmp = relu(acc + b1)
#pragma unroll
    for (int mi = 0; mi < 2; mi++) {
        int r0 = wm + mi * 16 + g;
        int r1 = r0 + 8;
#pragma unroll
        for (int ni = 0; ni < 8; ni++) {
            int col = wn + ni * 8 + tq * 2;
            float c0 = __ldg(b1 + col);
            float c1 = __ldg(b1 + col + 1);
            float v0 = fmaxf(acc[mi][ni][0] + c0, 0.f);
            float v1 = fmaxf(acc[mi][ni][1] + c1, 0.f);
            float v2 = fmaxf(acc[mi][ni][2] + c0, 0.f);
            float v3 = fmaxf(acc[mi][ni][3] + c1, 0.f);
            *(__half2*)(tmp + r0 * FTMP_STRIDE + col) = __floats2half2_rn(v0, v1);
            *(__half2*)(tmp + r1 * FTMP_STRIDE + col) = __floats2half2_rn(v2, v3);
            acc[mi][ni][0] = 0.f; acc[mi][ni][1] = 0.f;
            acc[mi][ni][2] = 0.f; acc[mi][ni][3] = 0.f;
        }
    }

    // phase 2: acc = tmp @ W2
#pragma unroll 1
    for (int i = 0; i < 4; i++) {
        if (i < 3) {
            fillB(buf ^ 1, (i + 1) * 64, W2p);
            cp_commit();
            cp_wait<1>();
        } else {
            cp_wait<0>();
        }
        __syncthreads();

        const __half2* Bb = hB + buf * FB_TILE2;
#pragma unroll
        for (int kk = 0; kk < 4; kk++) {
            uint32_t af[2][4];
#pragma unroll
            for (int mi = 0; mi < 2; mi++)
                ldsm4(af[mi], sbT + ((wm + mi * 16 + lrow) * FTMP_STRIDE + i * 64 + kk * 16 + lcol) * 2);
            uint32_t bf[8][2];
#pragma unroll
            for (int ni = 0; ni < 8; ni++) {
                const __half2* p = Bb + (kk * 8 + tq) * FB2_STRIDE + wn + ni * 8 + g;
                bf[ni][0] = *(const uint32_t*)(p);
                bf[ni][1] = *(const uint32_t*)(p + 4 * FB2_STRIDE);
            }
#pragma unroll
            for (int mi = 0; mi < 2; mi++)
#pragma unroll
                for (int ni = 0; ni < 8; ni++)
                    mma_f16(acc[mi][ni], af[mi], bf[ni]);
        }
        __syncthreads();
        buf ^= 1;
    }

    // phase 2 epilogue: Z(global) + z(tmp smem)
#pragma unroll
    for (int mi = 0; mi < 2; mi++) {
        int rr0 = wm + mi * 16 + g;
        int rr1 = rr0 + 8;
        int r0 = m0 + rr0;
        int r1 = m0 + rr1;
#pragma unroll
        for (int ni = 0; ni < 8; ni++) {
            int col = wn + ni * 8 + tq * 2;
            float c0 = __ldg(b2 + col);
            float c1 = __ldg(b2 + col + 1);
            __half2 z0 = __floats2half2_rn(acc[mi][ni][0] + c0, acc[mi][ni][1] + c1);
            __half2 z1 = __floats2half2_rn(acc[mi][ni][2] + c0, acc[mi][ni][3] + c1);
            *(__half2*)(tmp + rr0 * FTMP_STRIDE + col) = z0;
            *(__half2*)(tmp + rr1 * FTMP_STRIDE + col) = z1;
            if (r0 < M) *(__half2*)(Z + (size_t)r0 * 256 + col) = z0;
            if (r1 < M) *(__half2*)(Z + (size_t)r1 * 256 + col) = z1;
        }
    }
    __syncthreads();

    // phase 3: per-graph + chip stats from smem z
    {
        const int c = tid & 255;
        const int rbeg = (tid >> 8) * 64;
        const int* sbatch = (const int*)smemc;
        float ts = 0.f, tqs = 0.f;
        int curg = -1;
        float s = 0.f, q = 0.f;
        for (int r = rbeg; r < rbeg + 64; r++) {
            if (m0 + r >= M) break;
            int gg = sbatch[r];
            if (gg != curg) {
                if (curg >= 0) {
                    atomicAdd(gsum + (size_t)curg * 256 + c, s);
                    atomicAdd(gsq + (size_t)curg * 256 + c, q);
                }
                curg = gg; s = 0.f; q = 0.f;
            }
            float v = __half2float(tmp[r * FTMP_STRIDE + c]);
            s += v; q = fmaf(v, v, q);
            ts += v; tqs = fmaf(v, v, tqs);
        }
        if (curg >= 0) {
            atomicAdd(gsum + (size_t)curg * 256 + c, s);
            atomicAdd(gsq + (size_t)curg * 256 + c, q);
        }
        atomicAdd(stats + c, ts);
        atomicAdd(stats + 256 + c, tqs);
    }
}

// ===================== merged msq + normalize (block per graph) ================
__global__ void msq_norm_kernel(const float* __restrict__ stats,
                                const float* __restrict__ gamma,
                                const float* __restrict__ cnt,
                                const float* __restrict__ gsum,
                                const float* __restrict__ gsq,
                                const int* __restrict__ gstart,
                                const __half* __restrict__ zh,
                                __half* __restrict__ hout)
{
    __shared__ float red[HID];
    int gb = blockIdx.x;
    int c = threadIdx.x;
    const float invN = 1.0f / (float)NNODES;
    float mu = __ldg(stats + c) * invN;
    float var = __ldg(stats + HID + c) * invN - mu * mu;
    float ac = __ldg(gamma + c) * rsqrtf(var + 1e-5f);
    float cg = cnt[gb];
    size_t gi = (size_t)gb * HID + c;
    float S = gsum[gi], Q = gsq[gi];
    float m = S / cg;
    red[c] = ac * ac * (Q - cg * m * m);
    __syncthreads();
    for (int o = HID / 2; o > 0; o >>= 1) {
        if (c < o) red[c] += red[c + o];
        __syncthreads();
    }
    float sc = rsqrtf(1e-5f + red[0] / cg);
    int lo = gstart[gb], hi = gstart[gb + 1];
    float acs = ac * sc;
    for (int n = lo; n < hi; n++) {
        size_t i = (size_t)n * HID + c;
        float v = acs * (__half2float(zh[i]) - m);
        hout[i] = __float2half(fmaxf(v, 0.f));
    }
}

// ===================== fp16 GEMM (attention, tanh) =============================
#define HA_STRIDE 72
#define HA_TILE_BYTES (128 * HA_STRIDE * 2)

__global__ __launch_bounds__(256, 2) void hgemm_att(
    int M, const __half* __restrict__ A, const __half2* __restrict__ Bp,
    const float* __restrict__ bias, __half* __restrict__ Ch)
{
    constexpr int WN = 128;
    constexpr int HB2_STRIDE = WN + 4;
    constexpr int HB_TILE2 = 32 * HB2_STRIDE;
    const __half2* hB = (const __half2*)(smemc + 2 * HA_TILE_BYTES);
    uint32_t sb = (uint32_t)__cvta_generic_to_shared(smemc);
    uint32_t sbB = sb + 2 * HA_TILE_BYTES;

    const int tid = threadIdx.x;
    const int warp = tid >> 5;
    const int lane = tid & 31;
    const int g = lane >> 2;
    const int tq = lane & 3;
    const int m0 = blockIdx.y * 128;
    const int wm = (warp >> 1) * 32;
    const int wn = (warp & 1) * 64;
    const int lrow = ((lane >> 3) & 1) * 8 + (lane & 7);
    const int lcol = (lane >> 4) * 8;

    float acc[2][8][4];
#pragma unroll
    for (int i = 0; i < 2; i++)
#pragma unroll
        for (int j = 0; j < 8; j++)
#pragma unroll
            for (int r = 0; r < 4; r++) acc[i][j][r] = 0.0f;

    auto fillA = [&](int buf, int k0) {
#pragma unroll
        for (int it = 0; it < 4; it++) {
            int chunk = tid + it * 256;
            int r = chunk >> 3, c = (chunk & 7) * 8;
            bool p = (m0 + r) < M;
            cp16s(sb + buf * HA_TILE_BYTES + (r * HA_STRIDE + c) * 2,
                  A + (size_t)(p ? m0 + r : 0) * 256 + k0 + c, p);
        }
    };
    auto fillB = [&](int buf, int k0) {
#pragma unroll
        for (int it = 0; it < 4; it++) {
            int chunk = tid + it * 256;
            int pr = chunk >> 5, c2 = (chunk & 31) * 4;
            cp16s(sbB + (buf * HB_TILE2 + pr * HB2_STRIDE + c2) * 4,
                  Bp + (size_t)((k0 >> 1) + pr) * WN + c2, true);
        }
    };

    fillA(0, 0);
    fillB(0, 0);
    cp_commit();

    int buf = 0;
#pragma unroll 1
    for (int i = 0; i < 4; i++) {
        if (i + 1 < 4) {
            fillA(buf ^ 1, (i + 1) * 64);
            fillB(buf ^ 1, (i + 1) * 64);
            cp_commit();
            cp_wait<1>();
        } else {
            cp_wait<0>();
        }
        __syncthreads();

        uint32_t abase = sb + buf * HA_TILE_BYTES;
        const __half2* Bb = hB + buf * HB_TILE2;
#pragma unroll
        for (int kk = 0; kk < 4; kk++) {
            uint32_t af[2][4];
#pragma unroll
            for (int mi = 0; mi < 2; mi++)
                ldsm4(af[mi], abase + ((wm + mi * 16 + lrow) * HA_STRIDE + kk * 16 + lcol) * 2);
            uint32_t bf[8][2];
#pragma unroll
            for (int ni = 0; ni < 8; ni++) {
                const __half2* p = Bb + (kk * 8 + tq) * HB2_STRIDE + wn + ni * 8 + g;
                bf[ni][0] = *(const uint32_t*)(p);
                bf[ni][1] = *(const uint32_t*)(p + 4 * HB2_STRIDE);
            }
#pragma unroll
            for (int mi = 0; mi < 2; mi++)
#pragma unroll
                for (int ni = 0; ni < 8; ni++)
                    mma_f16(acc[mi][ni], af[mi], bf[ni]);
        }
        __syncthreads();
        buf ^= 1;
    }

#pragma unroll
    for (int mi = 0; mi < 2; mi++) {
        int r0 = m0 + wm + mi * 16 + g;
        int r1 = r0 + 8;
#pragma unroll
        for (int ni = 0; ni < 8; ni++) {
            int col = wn + ni * 8 + tq * 2;
            float b0 = __ldg(bias + col);
            float b1 = __ldg(bias + col + 1);
            float v0 = tanhf(acc[mi][ni][0] + b0);
            float v1 = tanhf(acc[mi][ni][1] + b1);
            float v2 = tanhf(acc[mi][ni][2] + b0);
            float v3 = tanhf(acc[mi][ni][3] + b1);
            if (r0 < M) *(__half2*)(Ch + (size_t)r0 * WN + col) = __floats2half2_rn(v0, v1);
            if (r1 < M) *(__half2*)(Ch + (size_t)r1 * WN + col) = __floats2half2_rn(v2, v3);
        }
    }
}

// ---------------- weight packs ---------------------------------------------------
__global__ void wpack_kernel(const float* __restrict__ w1, const float* __restrict__ w2,
                             __half2* __restrict__ w1p, __half2* __restrict__ w2p)
{
    int idx = blockIdx.x * 256 + threadIdx.x;
    int l = idx >> 15;
    int rem = idx & 32767;
    int p = rem >> 8;
    int n = rem & 255;
    size_t base = (size_t)l * 65536 + (size_t)(2 * p) * 256 + n;
    w1p[idx] = __floats2half2_rn(__ldg(w1 + base), __ldg(w1 + base + 256));
    w2p[idx] = __floats2half2_rn(__ldg(w2 + base), __ldg(w2 + base + 256));
}
__global__ void wpack_att_kernel(const float* __restrict__ w, __half2* __restrict__ wp)
{
    int idx = blockIdx.x * 256 + threadIdx.x;
    int p = idx >> 7;
    int n = idx & 127;
    size_t base = (size_t)(2 * p) * 128 + n;
    wp[idx] = __floats2half2_rn(__ldg(w + base), __ldg(w + base + 128));
}

// ===================== mma.sync TF32 GEMM (node embed) ========================
#define GA_STRIDE 36
#define GB_STRIDE 132
#define A_TILE_W (128 * GA_STRIDE)
#define B_TILE_W (32 * GB_STRIDE)
#define GEMM_SMEM_BYTES ((2 * A_TILE_W + 2 * B_TILE_W) * 4)

__device__ __forceinline__ void cp16(float* dst, const float* src, bool pred) {
    cp16s((uint32_t)__cvta_generic_to_shared(dst), src, pred);
}
__device__ __forceinline__ void mma_tf32(float* c, const uint32_t* a, const uint32_t* b) {
    asm volatile(
        "mma.sync.aligned.m16n8k8.row.col.f32.tf32.tf32.f32 "
        "{%0,%1,%2,%3}, {%4,%5,%6,%7}, {%8,%9}, {%0,%1,%2,%3};"
        : "+f"(c[0]), "+f"(c[1]), "+f"(c[2]), "+f"(c[3])
        : "r"(a[0]), "r"(a[1]), "r"(a[2]), "r"(a[3]), "r"(b[0]), "r"(b[1]));
}

__global__ __launch_bounds__(256, 2) void tf32_gemm_h(
    int M, int N, int K,
    const float* __restrict__ A, const float* __restrict__ B,
    const float* __restrict__ bias, __half* __restrict__ Chh)
{
    float* sm = (float*)smemc;
    float* As = sm;
    float* Bs = sm + 2 * A_TILE_W;

    const int tid = threadIdx.x;
    const int warp = tid >> 5;
    const int lane = tid & 31;
    const int g = lane >> 2;
    const int tq = lane & 3;
    const int m0 = blockIdx.y * 128;
    const int n0 = blockIdx.x * 128;
    const int wm = (warp >> 1) * 32;
    const int wn = (warp & 1) * 64;

    float acc[2][8][4];
#pragma unroll
    for (int i = 0; i < 2; i++)
#pragma unroll
        for (int j = 0; j < 8; j++)
#pragma unroll
            for (int r = 0; r < 4; r++) acc[i][j][r] = 0.0f;

    const int arow = tid >> 3;
    const int ac4 = tid & 7;
    const int brow = tid >> 5;
    const int bc4 = tid & 31;
    const int nk = (K + 31) / 32;

    {
#pragma unroll
        for (int it = 0; it < 4; it++) {
            int row = arow + it * 32;
            int gm = m0 + row;
            int gk = ac4 * 4;
            bool p = (gm < M) && (gk < K);
            const float* src = A + (size_t)(p ? gm : 0) * K + (p ? gk : 0);
            cp16(As + row * GA_STRIDE + ac4 * 4, src, p);
        }
#pragma unroll
        for (int it = 0; it < 4; it++) {
            int row = brow + it * 8;
            bool p = (row < K);
            const float* src = B + (size_t)(p ? row : 0) * N + n0 + bc4 * 4;
            cp16(Bs + row * GB_STRIDE + bc4 * 4, src, p);
        }
        cp_commit();
    }

    int buf = 0;
    for (int i = 0; i < nk; i++) {
        if (i + 1 < nk) {
            const int kc = i + 1;
            float* Ad = As + (buf ^ 1) * A_TILE_W;
            float* Bd = Bs + (buf ^ 1) * B_TILE_W;
#pragma unroll
            for (int it = 0; it < 4; it++) {
                int row = arow + it * 32;
                int gm = m0 + row;
                int gk = kc * 32 + ac4 * 4;
                bool p = (gm < M) && (gk < K);
                const float* src = A + (size_t)(p ? gm : 0) * K + (p ? gk : 0);
                cp16(Ad + row * GA_STRIDE + ac4 * 4, src, p);
            }
#pragma unroll
            for (int it = 0; it < 4; it++) {
                int row = brow + it * 8;
                int gk = kc * 32 + row;
                bool p = (gk < K);
                const float* src = B + (size_t)(p ? gk : 0) * N + n0 + bc4 * 4;
                cp16(Bd + row * GB_STRIDE + bc4 * 4, src, p);
            }
            cp_commit();
            cp_wait<1>();
        } else {
            cp_wait<0>();
        }
        __syncthreads();

        const float* Ab = As + buf * A_TILE_W;
        const float* Bb = Bs + buf * B_TILE_W;
#pragma unroll
        for (int kk = 0; kk < 4; kk++) {
            const int k = kk * 8;
            uint32_t af[2][4];
#pragma unroll
            for (int mi = 0; mi < 2; mi++) {
                const float* p = Ab + (wm + mi * 16 + g) * GA_STRIDE + k + tq;
                af[mi][0] = f2tf32(p[0]);
                af[mi][1] = f2tf32(p[8 * GA_STRIDE]);
                af[mi][2] = f2tf32(p[4]);
                af[mi][3] = f2tf32(p[8 * GA_STRIDE + 4]);
            }
            uint32_t bf[8][2];
#pragma unroll
            for (int ni = 0; ni < 8; ni++) {
                const float* p = Bb + (k + tq) * GB_STRIDE + wn + ni * 8 + g;
                bf[ni][0] = f2tf32(p[0]);
                bf[ni][1] = f2tf32(p[4 * GB_STRIDE]);
            }
#pragma unroll
            for (int mi = 0; mi < 2; mi++)
#pragma unroll
                for (int ni = 0; ni < 8; ni++)
                    mma_tf32(acc[mi][ni], af[mi], bf[ni]);
        }
        __syncthreads();
        buf ^= 1;
    }

#pragma unroll
    for (int mi = 0; mi < 2; mi++) {
        int r0 = m0 + wm + mi * 16 + g;
        int r1 = r0 + 8;
#pragma unroll
        for (int ni = 0; ni < 8; ni++) {
            int col = n0 + wn + ni * 8 + tq * 2;
            float b0 = __ldg(bias + col);
            float b1 = __ldg(bias + col + 1);
            if (r0 < M) *(__half2*)(Chh + (size_t)r0 * N + col) =
                __floats2half2_rn(acc[mi][ni][0] + b0, acc[mi][ni][1] + b1);
            if (r1 < M) *(__half2*)(Chh + (size_t)r1 * N + col) =
                __floats2half2_rn(acc[mi][ni][2] + b0, acc[mi][ni][3] + b1);
        }
    }
}

// ---------------- fused edge weights ------------------------------------------
__global__ void wfuse_kernel(const float* __restrict__ edge_w,
                             const float* __restrict__ edge_b,
                             const float* __restrict__ conv_w,
                             const float* __restrict__ conv_b,
                             float* __restrict__ wf)
{
    int layer = blockIdx.x;
    int k = blockIdx.y;
    int c = threadIdx.x;
    const float* cw = conv_w + (size_t)layer * EDIM * HID;
    float s = 0.f;
    if (k < EDGE_F) {
        for (int j = 0; j < EDIM; j++)
            s = fmaf(__ldg(edge_w + k * EDIM + j), __ldg(cw + (size_t)j * HID + c), s);
    } else {
        for (int j = 0; j < EDIM; j++)
            s = fmaf(__ldg(edge_b + j), __ldg(cw + (size_t)j * HID + c), s);
        s += __ldg(conv_b + (size_t)layer * HID + c);
    }
    wf[((size_t)layer * 7 + k) * HID + c] = s;
}

// ---------------- CSR build (parallel scan) -------------------------------------
__global__ void deg_kernel(const int* __restrict__ dst, int* __restrict__ deg)
{
    int e = blockIdx.x * blockDim.x + threadIdx.x;
    if (e < NEDGES) atomicAdd(&deg[__ldg(dst + e)], 1);
}

__global__ void deg_bsum_kernel(const int* __restrict__ deg, int* __restrict__ bsum)
{
    __shared__ int sh[256];
    int i = blockIdx.x * 256 + threadIdx.x;
    sh[threadIdx.x] = (i < NNODES) ? deg[i] : 0;
    __syncthreads();
    for (int o = 128; o > 0; o >>= 1) {
        if (threadIdx.x < o) sh[threadIdx.x] += sh[threadIdx.x + o];
        __syncthreads();
    }
    if (threadIdx.x == 0) bsum[blockIdx.x] = sh[0];
}

__global__ void bscan_kernel(const int* __restrict__ bsum, int* __restrict__ boffs)
{
    __shared__ int sh[512];
    int t = threadIdx.x;
    int mine = (t < NBLKD) ? bsum[t] : 0;
    sh[t] = mine;
    __syncthreads();
    for (int o = 1; o < 512; o <<= 1) {
        int v = (t >= o) ? sh[t - o] : 0;
        __syncthreads();
        sh[t] += v;
        __syncthreads();
    }
    if (t < NBLKD) boffs[t] = sh[t] - mine;
}

__global__ void rowfill_kernel(const int* __restrict__ deg, const int* __restrict__ boffs,
                               int* __restrict__ rowstart, int* __restrict__ cursor)
{
    __shared__ int sh[256];
    int b = blockIdx.x, t = threadIdx.x;
    int i = b * 256 + t;
    int d = (i < NNODES) ? deg[i] : 0;
    sh[t] = d;
    __syncthreads();
    for (int o = 1; o < 256; o <<= 1) {
        int v = (t >= o) ? sh[t - o] : 0;
        __syncthreads();
        sh[t] += v;
        __syncthreads();
    }
    if (i < NNODES) {
        int rs = boffs[b] + sh[t] - d;
        rowstart[i] = rs;
        cursor[i] = rs;
    }
    if (i == NNODES - 1) rowstart[NNODES] = NEDGES;
}

__global__ void csr_fill_kernel(const int* __restrict__ src,
                                const int* __restrict__ dst,
                                int* __restrict__ cursor,
                                int* __restrict__ csr_eid,
                                int* __restrict__ csr_src)
{
    int e = blockIdx.x * blockDim.x + threadIdx.x;
    if (e >= NEDGES) return;
    int d = __ldg(dst + e);
    int p = atomicAdd(&cursor[d], 1);
    csr_eid[p] = e;
    csr_src[p] = __ldg(src + e);
}

// ---------------- permute edge attrs into CSR order ----------------------------
__global__ void eaperm_kernel(const float* __restrict__ ea,
                              const int* __restrict__ csr_eid,
                              float* __restrict__ eap)
{
    int j = blockIdx.x * blockDim.x + threadIdx.x;
    if (j >= NEDGES) return;
    int eid = __ldg(csr_eid + j);
    const float* e = ea + (size_t)eid * EDGE_F;
    float4 a = make_float4(__ldg(e), __ldg(e + 1), __ldg(e + 2), __ldg(e + 3));
    float2 b = make_float2(__ldg(e + 4), __ldg(e + 5));
    *(float4*)(eap + (size_t)j * 8) = a;
    *(float2*)(eap + (size_t)j * 8 + 4) = b;
}

// ---------------- graph ranges --------------------------------------------------
__global__ void gstart_min_kernel(const int* __restrict__ batch, int* __restrict__ gstart)
{
    int n = blockIdx.x * blockDim.x + threadIdx.x;
    if (n < NNODES) atomicMin(&gstart[__ldg(batch + n)], n);
}

__global__ void gstart_fix_kernel(int* __restrict__ gstart, float* __restrict__ cnt)
{
    __shared__ int sg[NGRAPH + 1];
    int t = threadIdx.x;
    for (int i = t; i <= NGRAPH; i += 1024) sg[i] = gstart[i];
    __syncthreads();
    if (t == 0) {
        sg[NGRAPH] = NNODES;
        for (int g2 = NGRAPH - 1; g2 >= 0; g2--)
            if (sg[g2] > sg[g2 + 1]) sg[g2] = sg[g2 + 1];
    }
    __syncthreads();
    for (int i = t; i <= NGRAPH; i += 1024) gstart[i] = sg[i];
    for (int i = t; i < NGRAPH; i += 1024)
        cnt[i] = fmaxf((float)(sg[i + 1] - sg[i]), 1.0f);
}

// ---------------- GINE gather v3b: permuted ea + full 1-edge pipeline -----------
__device__ __forceinline__ float4 h4load(const uint2* hp, int idx) {
    uint2 u = __ldg(hp + idx);
    float2 f0 = __half22float2(*(__half2*)&u.x);
    float2 f1 = __half22float2(*(__half2*)&u.y);
    return make_float4(f0.x, f0.y, f1.x, f1.y);
}

__global__ __launch_bounds__(256) void gine_gather_fused(
    const __half* __restrict__ h,
    const float* __restrict__ eap,
    const int* __restrict__ rowstart,
    const int* __restrict__ csr_src,
    const float* __restrict__ wf,
    const float* __restrict__ eps_ptr,
    __half* __restrict__ aeffh,
    float* __restrict__ stats,
    float* __restrict__ gsum,
    float* __restrict__ gsq)
{
    {
        int gid = blockIdx.x * 256 + threadIdx.x;
        if (gid < 262144) {
            gsum[gid] = 0.f; gsum[gid + 262144] = 0.f;
            gsq[gid] = 0.f;  gsq[gid + 262144] = 0.f;
        }
        if (blockIdx.x == 0) {
            stats[threadIdx.x] = 0.f;
            stats[256 + threadIdx.x] = 0.f;
        }
    }

    const int t = threadIdx.x & 63;
    const int group = (blockIdx.x * blockDim.x + threadIdx.x) >> 6;
    const int ngroups = (gridDim.x * blockDim.x) >> 6;
    const float alpha = 1.0f + __ldg(eps_ptr);

    float4 w[EDGE_F];
#pragma unroll
    for (int k = 0; k < EDGE_F; k++)
        w[k] = __ldg((const float4*)(wf + k * HID) + t);
    float4 bf = __ldg((const float4*)(wf + EDGE_F * HID) + t);

    for (int n = group; n < NNODES; n += ngroups) {
        float4 a = h4load((const uint2*)(h + (size_t)n * HID), t);
        a.x *= alpha; a.y *= alpha; a.z *= alpha; a.w *= alpha;

        int lo = __ldg(rowstart + n), hi = __ldg(rowstart + n + 1);
        int s_next = 0;
        float4 e03n = make_float4(0.f, 0.f, 0.f, 0.f);
        float2 e45n = make_float2(0.f, 0.f);
        if (lo < hi) {
            s_next = __ldg(csr_src + lo);
            e03n = __ldg((const float4*)(eap + (size_t)lo * 8));
            e45n = __ldg((const float2*)(eap + (size_t)lo * 8 + 4));
        }
        for (int j = lo; j < hi; j++) {
            int s_cur = s_next;
            float4 e03 = e03n;
            float2 e45 = e45n;
            if (j + 1 < hi) {
                s_next = __ldg(csr_src + j + 1);
                e03n = __ldg((const float4*)(eap + (size_t)(j + 1) * 8));
                e45n = __ldg((const float2*)(eap + (size_t)(j + 1) * 8 + 4));
            }
            float4 hv = h4load((const uint2*)(h + (size_t)s_cur * HID), t);

            float4 ee = bf;
            ee.x = fmaf(e03.x, w[0].x, ee.x); ee.y = fmaf(e03.x, w[0].y, ee.y);
            ee.z = fmaf(e03.x, w[0].z, ee.z); ee.w = fmaf(e03.x, w[0].w, ee.w);
            ee.x = fmaf(e03.y, w[1].x, ee.x); ee.y = fmaf(e03.y, w[1].y, ee.y);
            ee.z = fmaf(e03.y, w[1].z, ee.z); ee.w = fmaf(e03.y, w[1].w, ee.w);
            ee.x = fmaf(e03.z, w[2].x, ee.x); ee.y = fmaf(e03.z, w[2].y, ee.y);
            ee.z = fmaf(e03.z, w[2].z, ee.z); ee.w = fmaf(e03.z, w[2].w, ee.w);
            ee.x = fmaf(e03.w, w[3].x, ee.x); ee.y = fmaf(e03.w, w[3].y, ee.y);
            ee.z = fmaf(e03.w, w[3].z, ee.z); ee.w = fmaf(e03.w, w[3].w, ee.w);
            ee.x = fmaf(e45.x, w[4].x, ee.x); ee.y = fmaf(e45.x, w[4].y, ee.y);
            ee.z = fmaf(e45.x, w[4].z, ee.z); ee.w = fmaf(e45.x, w[4].w, ee.w);
            ee.x = fmaf(e45.y, w[5].x, ee.x); ee.y = fmaf(e45.y, w[5].y, ee.y);
            ee.z = fmaf(e45.y, w[5].z, ee.z); ee.w = fmaf(e45.y, w[5].w, ee.w);

            a.x += fmaxf(hv.x + ee.x, 0.f);
            a.y += fmaxf(hv.y + ee.y, 0.f);
            a.z += fmaxf(hv.z + ee.z, 0.f);
            a.w += fmaxf(hv.w + ee.w, 0.f);
        }
        __half2* ap = (__half2*)(aeffh + (size_t)n * HID);
        ap[2 * t]     = __floats2half2_rn(a.x, a.y);
        ap[2 * t + 1] = __floats2half2_rn(a.z, a.w);
    }
}

// ---------------- merged attention + pooling (block per graph) -----------------
__global__ void pool_att_kernel(const __half* __restrict__ h,
                                const __half* __restrict__ s1,
                                const float* __restrict__ w2,
                                const float* __restrict__ b2,
                                const int* __restrict__ gstart,
                                const float* __restrict__ cnt,
                                float* __restrict__ out)
{
    __shared__ float swexp[128];
    __shared__ float sw2[128];
    __shared__ float swsum;
    int g = blockIdx.x;
    int t = threadIdx.x;
    int warp = t >> 5, lane = t & 31;
    if (t < 128) sw2[t] = __ldg(w2 + t);
    if (t == 0) swsum = 0.f;
    float b2v = __ldg(b2);
    int lo = gstart[g], hi = gstart[g + 1];
    float s = 0.f, mx = 0.f, att = 0.f;
    __syncthreads();

    for (int c0 = lo; c0 < hi; c0 += 128) {
        int nchunk = min(128, hi - c0);
        for (int j = warp; j < nchunk; j += 8) {
            const __half2* sp = (const __half2*)(s1 + (size_t)(c0 + j) * EDIM);
            float acc = 0.f;
#pragma unroll
            for (int k = lane; k < 64; k += 32) {
                float2 f = __half22float2(__ldg(sp + k));
                acc = fmaf(f.x, sw2[2 * k], acc);
                acc = fmaf(f.y, sw2[2 * k + 1], acc);
            }
#pragma unroll
            for (int o = 16; o > 0; o >>= 1) acc += __shfl_down_sync(0xffffffffu, acc, o);
            if (lane == 0) swexp[j] = expf(acc + b2v);
        }
        __syncthreads();
        if (t < 32) {
            float wv = 0.f;
            for (int j = t; j < nchunk; j += 32) wv += swexp[j];
#pragma unroll
            for (int o = 16; o > 0; o >>= 1) wv += __shfl_down_sync(0xffffffffu, wv, o);
            if (t == 0) swsum += wv;
        }
        for (int j = 0; j < nchunk; j++) {
            float v = __half2float(__ldg(h + (size_t)(c0 + j) * HID + t));
            s += v;
            mx = fmaxf(mx, v);
            att = fmaf(v, swexp[j], att);
        }
        __syncthreads();
    }
    float* og = out + (size_t)g * (3 * HID);
    og[t] = s / cnt[g];
    og[HID + t] = mx;
    og[2 * HID + t] = att / (swsum + 1e-8f);
}

// ---------------- host launch --------------------------------------------------------
extern "C" void kernel_launch(void* const* d_in, const int* in_sizes, int n_in,
                              void* d_out, int out_size)
{
    const float* x         = (const float*)d_in[0];
    const float* edge_attr = (const float*)d_in[1];
    const float* node_w    = (const float*)d_in[2];
    const float* node_b    = (const float*)d_in[3];
    const float* edge_w    = (const float*)d_in[4];
    const float* edge_b    = (const float*)d_in[5];
    const float* conv_w    = (const float*)d_in[6];
    const float* conv_b    = (const float*)d_in[7];
    const float* mlp_w1    = (const float*)d_in[8];
    const float* mlp_b1    = (const float*)d_in[9];
    const float* mlp_w2    = (const float*)d_in[10];
    const float* mlp_b2    = (const float*)d_in[11];
    const float* eps       = (const float*)d_in[12];
    const float* bn_gamma  = (const float*)d_in[13];
    const float* bn_beta   = (const float*)d_in[14];
    const float* att_w1    = (const float*)d_in[15];
    const float* att_b1    = (const float*)d_in[16];
    const float* att_w2    = (const float*)d_in[17];
    const float* att_b2    = (const float*)d_in[18];
    const int*   edge_index= (const int*)d_in[19];
    const int*   batch     = (const int*)d_in[20];
    float* out = (float*)d_out;
    (void)bn_beta;   // cancels exactly under PairNorm centering

    const int* src = edge_index;
    const int* dst = edge_index + NEDGES;

    const int HG_SMEM_128 = 2 * HA_TILE_BYTES + 2 * 32 * (128 + 4) * 4;

    cudaFuncSetAttribute(tf32_gemm_h, cudaFuncAttributeMaxDynamicSharedMemorySize, GEMM_SMEM_BYTES);
    cudaFuncSetAttribute(fused_mlp, cudaFuncAttributeMaxDynamicSharedMemorySize, FUSED_SMEM);
    cudaFuncSetAttribute(hgemm_att, cudaFuncAttributeMaxDynamicSharedMemorySize, HG_SMEM_128);

    float *p_stats, *p_gsum, *p_gsq, *p_cnt, *p_wf, *p_eap;
    __half *p_hh0, *p_hh1, *p_zh, *p_aeffh, *p_s1h;
    __half2 *p_w1p, *p_w2p, *p_w1a;
    int *p_deg, *p_bsum, *p_boffs, *p_rowstart, *p_cursor, *p_eid, *p_csrc, *p_gstart;
    cudaGetSymbolAddress((void**)&p_hh0, g_hh0);
    cudaGetSymbolAddress((void**)&p_hh1, g_hh1);
    cudaGetSymbolAddress((void**)&p_zh, g_zh);
    cudaGetSymbolAddress((void**)&p_aeffh, g_aeffh);
    cudaGetSymbolAddress((void**)&p_s1h, g_s1h);
    cudaGetSymbolAddress((void**)&p_w1p, g_w1p);
    cudaGetSymbolAddress((void**)&p_w2p, g_w2p);
    cudaGetSymbolAddress((void**)&p_w1a, g_w1a);
    cudaGetSymbolAddress((void**)&p_eap, g_eap);
    cudaGetSymbolAddress((void**)&p_stats, g_stats);
    cudaGetSymbolAddress((void**)&p_gsum, g_gsum);
    cudaGetSymbolAddress((void**)&p_gsq, g_gsq);
    cudaGetSymbolAddress((void**)&p_cnt, g_cnt);
    cudaGetSymbolAddress((void**)&p_wf, g_wf);
    cudaGetSymbolAddress((void**)&p_deg, g_deg);
    cudaGetSymbolAddress((void**)&p_bsum, g_bsum);
    cudaGetSymbolAddress((void**)&p_boffs, g_boffs);
    cudaGetSymbolAddress((void**)&p_rowstart, g_rowstart);
    cudaGetSymbolAddress((void**)&p_cursor, g_cursor);
    cudaGetSymbolAddress((void**)&p_eid, g_csr_eid);
    cudaGetSymbolAddress((void**)&p_csrc, g_csr_src);
    cudaGetSymbolAddress((void**)&p_gstart, g_gstart);

    // ----- CSR build (parallel scan)
    cudaMemsetAsync(p_deg, 0, NNODES * sizeof(int));
    deg_kernel<<<(NEDGES + 255) / 256, 256>>>(dst, p_deg);
    deg_bsum_kernel<<<NBLKD, 256>>>(p_deg, p_bsum);
    bscan_kernel<<<1, 512>>>(p_bsum, p_boffs);
    rowfill_kernel<<<NBLKD, 256>>>(p_deg, p_boffs, p_rowstart, p_cursor);
    csr_fill_kernel<<<(NEDGES + 255) / 256, 256>>>(src, dst, p_cursor, p_eid, p_csrc);
    eaperm_kernel<<<(NEDGES + 255) / 256, 256>>>(edge_attr, p_eid, p_eap);

    // ----- graph ranges + counts
    cudaMemsetAsync(p_gstart, 0x7F, (NGRAPH + 1) * sizeof(int));
    gstart_min_kernel<<<(NNODES + 255) / 256, 256>>>(batch, p_gstart);
    gstart_fix_kernel<<<1, 1024>>>(p_gstart, p_cnt);

    // ----- weight prep
    wfuse_kernel<<<dim3(NLAYER, 7), HID>>>(edge_w, edge_b, conv_w, conv_b, p_wf);
    wpack_kernel<<<(NLAYER * 128 * 256) / 256, 256>>>(mlp_w1, mlp_w2, p_w1p, p_w2p);
    wpack_att_kernel<<<(128 * 128) / 256, 256>>>(att_w1, p_w1a);

    // ----- node embedding (tf32, half output)
    {
        dim3 grid(HID / 128, (NNODES + 127) / 128);
        tf32_gemm_h<<<grid, 256, GEMM_SMEM_BYTES>>>(NNODES, HID, NODE_F, x, node_w,
                                                    node_b, p_hh0);
    }

    __half* h_cur = p_hh0;
    __half* h_nxt = p_hh1;
    const int mgrid = (NNODES + 127) / 128;

    for (int i = 0; i < NLAYER; i++) {
        gine_gather_fused<<<2048, 256>>>(
            h_cur, p_eap, p_rowstart, p_csrc,
            p_wf + (size_t)i * 7 * HID, eps + i, p_aeffh, p_stats, p_gsum, p_gsq);

        fused_mlp<<<mgrid, 512, FUSED_SMEM>>>(
            NNODES, p_aeffh,
            p_w1p + (size_t)i * 32768, p_w2p + (size_t)i * 32768,
            mlp_b1 + (size_t)i * HID, mlp_b2 + (size_t)i * HID,
            batch, p_gsum, p_gsq, p_stats, p_zh);

        msq_norm_kernel<<<NGRAPH, HID>>>(p_stats, bn_gamma + (size_t)i * HID,
                                         p_cnt, p_gsum, p_gsq, p_gstart, p_zh, h_nxt);

        __half* t = h_cur; h_cur = h_nxt; h_nxt = t;
    }

    // attention hidden: s1 = tanh(h @ att_w1 + att_b1)
    {
        dim3 agrid(1, (NNODES + 127) / 128);
        hgemm_att<<<agrid, 256, HG_SMEM_128>>>(NNODES, h_cur, p_w1a, att_b1, p_s1h);
    }

    // merged attention-score + pooling
    pool_att_kernel<<<NGRAPH, HID>>>(h_cur, p_s1h, att_w2, att_b2, p_gstart, p_cnt, out);

    (void)in_sizes; (void)n_in; (void)out_size;
}

// round 14
// speedup vs baseline: 1.1763x; 1.0107x over previous
#include <cuda_runtime.h>
#include <cuda_fp16.h>
#include <math.h>
#include <stdint.h>

#define NNODES 100000
#define NEDGES 320000
#define NGRAPH 2048
#define HID    256
#define EDIM   128
#define NODE_F 48
#define EDGE_F 6
#define NLAYER 8
#define NBLKD  ((NNODES + 255) / 256)   // 391

// ---------------- scratch (device globals) ----------------------------------
__device__ __half  g_hh0[(size_t)NNODES * HID];
__device__ __half  g_hh1[(size_t)NNODES * HID];
__device__ __half  g_zh [(size_t)NNODES * HID];
__device__ __half  g_aeffh[(size_t)NNODES * HID];
__device__ __half  g_s1h [(size_t)NNODES * EDIM];
__device__ __half2 g_w1p[(size_t)NLAYER * (HID / 2) * HID];
__device__ __half2 g_w2p[(size_t)NLAYER * (HID / 2) * HID];
__device__ __half2 g_w1a[(size_t)(HID / 2) * EDIM];
__device__ float   g_eap[(size_t)NEDGES * 8];     // CSR-ordered edge attrs (padded)
__device__ float   g_stats[2 * HID];
__device__ float   g_gsum[(size_t)NGRAPH * HID];
__device__ float   g_gsq [(size_t)NGRAPH * HID];
__device__ float   g_cnt [NGRAPH];
__device__ float   g_wf  [(size_t)NLAYER * 7 * HID];
__device__ int     g_deg [NNODES];
__device__ int     g_bsum[NBLKD];
__device__ int     g_boffs[NBLKD];
__device__ int     g_rowstart[NNODES + 1];
__device__ int     g_cursor[NNODES];
__device__ int     g_csr_src[NEDGES];
__device__ int     g_gstart[NGRAPH + 1];

// ---------------- common helpers ---------------------------------------------
__device__ __forceinline__ uint32_t f2tf32(float x) {
    uint32_t r;
    asm volatile("cvt.rna.tf32.f32 %0, %1;" : "=r"(r) : "f"(x));
    return r;
}
__device__ __forceinline__ void cp16s(uint32_t d, const void* src, bool pred) {
    int sz = pred ? 16 : 0;
    asm volatile("cp.async.cg.shared.global [%0], [%1], 16, %2;" :: "r"(d), "l"(src), "r"(sz));
}
__device__ __forceinline__ void cp_commit() { asm volatile("cp.async.commit_group;"); }
template <int Np>
__device__ __forceinline__ void cp_wait() { asm volatile("cp.async.wait_group %0;" :: "n"(Np)); }
__device__ __forceinline__ void mma_f16(float* c, const uint32_t* a, const uint32_t* b) {
    asm volatile(
        "mma.sync.aligned.m16n8k16.row.col.f32.f16.f16.f32 "
        "{%0,%1,%2,%3}, {%4,%5,%6,%7}, {%8,%9}, {%0,%1,%2,%3};"
        : "+f"(c[0]), "+f"(c[1]), "+f"(c[2]), "+f"(c[3])
        : "r"(a[0]), "r"(a[1]), "r"(a[2]), "r"(a[3]), "r"(b[0]), "r"(b[1]));
}
__device__ __forceinline__ void ldsm4(uint32_t* r, uint32_t addr) {
    asm volatile("ldmatrix.sync.aligned.m8n8.x4.shared.b16 {%0,%1,%2,%3}, [%4];"
                 : "=r"(r[0]), "=r"(r[1]), "=r"(r[2]), "=r"(r[3]) : "r"(addr));
}

extern __shared__ char smemc[];

// ===================== fused MLP + stats ========================================
#define FA_STRIDE 72
#define FA_TILE_BYTES (128 * FA_STRIDE * 2)
#define FB2_STRIDE 260
#define FB_TILE2 (32 * FB2_STRIDE)
#define FTMP_STRIDE 264
#define OFF_B (2 * FA_TILE_BYTES)
#define OFF_TMP (OFF_B + 2 * FB_TILE2 * 4)
#define FUSED_SMEM (OFF_TMP + 128 * FTMP_STRIDE * 2)   // 171008

__global__ __launch_bounds__(512, 1) void fused_mlp(
    int M, const __half* __restrict__ A,
    const __half2* __restrict__ W1p, const __half2* __restrict__ W2p,
    const float* __restrict__ b1, const float* __restrict__ b2,
    const int* __restrict__ batchp,
    float* __restrict__ gsum, float* __restrict__ gsq, float* __restrict__ stats,
    __half* __restrict__ Z)
{
    uint32_t sb = (uint32_t)__cvta_generic_to_shared(smemc);
    const __half2* hB = (const __half2*)(smemc + OFF_B);
    __half* tmp = (__half*)(smemc + OFF_TMP);
    uint32_t sbT = sb + OFF_TMP;

    const int tid = threadIdx.x;
    const int warp = tid >> 5;
    const int lane = tid & 31;
    const int g = lane >> 2;
    const int tq = lane & 3;
    const int m0 = blockIdx.x * 128;
    const int wm = (warp & 3) * 32;
    const int wn = (warp >> 2) * 64;
    const int lrow = ((lane >> 3) & 1) * 8 + (lane & 7);
    const int lcol = (lane >> 4) * 8;

    float acc[2][8][4];
#pragma unroll
    for (int i = 0; i < 2; i++)
#pragma unroll
        for (int j = 0; j < 8; j++)
#pragma unroll
            for (int r = 0; r < 4; r++) acc[i][j][r] = 0.0f;

    auto fillA = [&](int buf, int k0) {
#pragma unroll
        for (int it = 0; it < 2; it++) {
            int chunk = tid + it * 512;
            int r = chunk >> 3, c = (chunk & 7) * 8;
            bool p = (m0 + r) < M;
            cp16s(sb + buf * FA_TILE_BYTES + (r * FA_STRIDE + c) * 2,
                  A + (size_t)(p ? m0 + r : 0) * 256 + k0 + c, p);
        }
    };
    auto fillB = [&](int buf, int k0, const __half2* W) {
#pragma unroll
        for (int it = 0; it < 4; it++) {
            int chunk = tid + it * 512;
            int pr = chunk >> 6, c2 = (chunk & 63) * 4;
            cp16s(sb + OFF_B + (buf * FB_TILE2 + pr * FB2_STRIDE + c2) * 4,
                  W + (size_t)((k0 >> 1) + pr) * 256 + c2, true);
        }
    };

    // phase 1: acc = A @ W1
    fillA(0, 0);
    fillB(0, 0, W1p);
    cp_commit();

    int buf = 0;
#pragma unroll 1
    for (int i = 0; i < 4; i++) {
        if (i < 3) {
            fillA(buf ^ 1, (i + 1) * 64);
            fillB(buf ^ 1, (i + 1) * 64, W1p);
        } else {
            fillB(buf ^ 1, 0, W2p);
        }
        cp_commit();
        cp_wait<1>();
        __syncthreads();

        uint32_t abase = sb + buf * FA_TILE_BYTES;
        const __half2* Bb = hB + buf * FB_TILE2;
#pragma unroll
        for (int kk = 0; kk < 4; kk++) {
            uint32_t af[2][4];
#pragma unroll
            for (int mi = 0; mi < 2; mi++)
                ldsm4(af[mi], abase + ((wm + mi * 16 + lrow) * FA_STRIDE + kk * 16 + lcol) * 2);
            uint32_t bf[8][2];
#pragma unroll
            for (int ni = 0; ni < 8; ni++) {
                const __half2* p = Bb + (kk * 8 + tq) * FB2_STRIDE + wn + ni * 8 + g;
                bf[ni][0] = *(const uint32_t*)(p);
                bf[ni][1] = *(const uint32_t*)(p + 4 * FB2_STRIDE);
            }
#pragma unroll
            for (int mi = 0; mi < 2; mi++)
#pragma unroll
                for (int ni = 0; ni < 8; ni++)
                    mma_f16(acc[mi][ni], af[mi], bf[ni]);
        }
        __syncthreads();
        buf ^= 1;
    }

    if (tid < 128)
        ((int*)smemc)[tid] = (m0 + tid < M) ? __ldg(batchp + m0 + tid) : 0;

    // phase 1 epilogue: tmp = relu(acc + b1)
#pragma unroll
    for (int mi = 0; mi < 2; mi++) {
        int r0 = wm + mi * 16 + g;
        int r1 = r0 + 8;
#pragma unroll
        for (int ni = 0; ni < 8; ni++) {
            int col = wn + ni * 8 + tq * 2;
            float c0 = __ldg(b1 + col);
            float c1 = __ldg(b1 + col + 1);
            float v0 = fmaxf(acc[mi][ni][0] + c0, 0.f);
            float v1 = fmaxf(acc[mi][ni][1] + c1, 0.f);
            float v2 = fmaxf(acc[mi][ni][2] + c0, 0.f);
            float v3 = fmaxf(acc[mi][ni][3] + c1, 0.f);
            *(__half2*)(tmp + r0 * FTMP_STRIDE + col) = __floats2half2_rn(v0, v1);
            *(__half2*)(tmp + r1 * FTMP_STRIDE + col) = __floats2half2_rn(v2, v3);
            acc[mi][ni][0] = 0.f; acc[mi][ni][1] = 0.f;
            acc[mi][ni][2] = 0.f; acc[mi][ni][3] = 0.f;
        }
    }

    // phase 2: acc = tmp @ W2
#pragma unroll 1
    for (int i = 0; i < 4; i++) {
        if (i < 3) {
            fillB(buf ^ 1, (i + 1) * 64, W2p);
            cp_commit();
            cp_wait<1>();
        } else {
            cp_wait<0>();
        }
        __syncthreads();

        const __half2* Bb = hB + buf * FB_TILE2;
#pragma unroll
        for (int kk = 0; kk < 4; kk++) {
            uint32_t af[2][4];
#pragma unroll
            for (int mi = 0; mi < 2; mi++)
                ldsm4(af[mi], sbT + ((wm + mi * 16 + lrow) * FTMP_STRIDE + i * 64 + kk * 16 + lcol) * 2);
            uint32_t bf[8][2];
#pragma unroll
            for (int ni = 0; ni < 8; ni++) {
                const __half2* p = Bb + (kk * 8 + tq) * FB2_STRIDE + wn + ni * 8 + g;
                bf[ni][0] = *(const uint32_t*)(p);
                bf[ni][1] = *(const uint32_t*)(p + 4 * FB2_STRIDE);
            }
#pragma unroll
            for (int mi = 0; mi < 2; mi++)
#pragma unroll
                for (int ni = 0; ni < 8; ni++)
                    mma_f16(acc[mi][ni], af[mi], bf[ni]);
        }
        __syncthreads();
        buf ^= 1;
    }

    // phase 2 epilogue: Z(global) + z(tmp smem)
#pragma unroll
    for (int mi = 0; mi < 2; mi++) {
        int rr0 = wm + mi * 16 + g;
        int rr1 = rr0 + 8;
        int r0 = m0 + rr0;
        int r1 = m0 + rr1;
#pragma unroll
        for (int ni = 0; ni < 8; ni++) {
            int col = wn + ni * 8 + tq * 2;
            float c0 = __ldg(b2 + col);
            float c1 = __ldg(b2 + col + 1);
            __half2 z0 = __floats2half2_rn(acc[mi][ni][0] + c0, acc[mi][ni][1] + c1);
            __half2 z1 = __floats2half2_rn(acc[mi][ni][2] + c0, acc[mi][ni][3] + c1);
            *(__half2*)(tmp + rr0 * FTMP_STRIDE + col) = z0;
            *(__half2*)(tmp + rr1 * FTMP_STRIDE + col) = z1;
            if (r0 < M) *(__half2*)(Z + (size_t)r0 * 256 + col) = z0;
            if (r1 < M) *(__half2*)(Z + (size_t)r1 * 256 + col) = z1;
        }
    }
    __syncthreads();

    // phase 3: per-graph + chip stats from smem z
    {
        const int c = tid & 255;
        const int rbeg = (tid >> 8) * 64;
        const int* sbatch = (const int*)smemc;
        float ts = 0.f, tqs = 0.f;
        int curg = -1;
        float s = 0.f, q = 0.f;
        for (int r = rbeg; r < rbeg + 64; r++) {
            if (m0 + r >= M) break;
            int gg = sbatch[r];
            if (gg != curg) {
                if (curg >= 0) {
                    atomicAdd(gsum + (size_t)curg * 256 + c, s);
                    atomicAdd(gsq + (size_t)curg * 256 + c, q);
                }
                curg = gg; s = 0.f; q = 0.f;
            }
            float v = __half2float(tmp[r * FTMP_STRIDE + c]);
            s += v; q = fmaf(v, v, q);
            ts += v; tqs = fmaf(v, v, tqs);
        }
        if (curg >= 0) {
            atomicAdd(gsum + (size_t)curg * 256 + c, s);
            atomicAdd(gsq + (size_t)curg * 256 + c, q);
        }
        atomicAdd(stats + c, ts);
        atomicAdd(stats + 256 + c, tqs);
    }
}

// ===================== merged msq + normalize (block per graph) ================
__global__ void msq_norm_kernel(const float* __restrict__ stats,
                                const float* __restrict__ gamma,
                                const float* __restrict__ cnt,
                                const float* __restrict__ gsum,
                                const float* __restrict__ gsq,
                                const int* __restrict__ gstart,
                                const __half* __restrict__ zh,
                                __half* __restrict__ hout)
{
    __shared__ float red[HID];
    int gb = blockIdx.x;
    int c = threadIdx.x;
    const float invN = 1.0f / (float)NNODES;
    float mu = __ldg(stats + c) * invN;
    float var = __ldg(stats + HID + c) * invN - mu * mu;
    float ac = __ldg(gamma + c) * rsqrtf(var + 1e-5f);
    float cg = cnt[gb];
    size_t gi = (size_t)gb * HID + c;
    float S = gsum[gi], Q = gsq[gi];
    float m = S / cg;
    red[c] = ac * ac * (Q - cg * m * m);
    __syncthreads();
    for (int o = HID / 2; o > 0; o >>= 1) {
        if (c < o) red[c] += red[c + o];
        __syncthreads();
    }
    float sc = rsqrtf(1e-5f + red[0] / cg);
    int lo = gstart[gb], hi = gstart[gb + 1];
    float acs = ac * sc;
    for (int n = lo; n < hi; n++) {
        size_t i = (size_t)n * HID + c;
        float v = acs * (__half2float(zh[i]) - m);
        hout[i] = __float2half(fmaxf(v, 0.f));
    }
}

// ===================== fp16 GEMM (attention, tanh) =============================
#define HA_STRIDE 72
#define HA_TILE_BYTES (128 * HA_STRIDE * 2)

__global__ __launch_bounds__(256, 2) void hgemm_att(
    int M, const __half* __restrict__ A, const __half2* __restrict__ Bp,
    const float* __restrict__ bias, __half* __restrict__ Ch)
{
    constexpr int WN = 128;
    constexpr int HB2_STRIDE = WN + 4;
    constexpr int HB_TILE2 = 32 * HB2_STRIDE;
    const __half2* hB = (const __half2*)(smemc + 2 * HA_TILE_BYTES);
    uint32_t sb = (uint32_t)__cvta_generic_to_shared(smemc);
    uint32_t sbB = sb + 2 * HA_TILE_BYTES;

    const int tid = threadIdx.x;
    const int warp = tid >> 5;
    const int lane = tid & 31;
    const int g = lane >> 2;
    const int tq = lane & 3;
    const int m0 = blockIdx.y * 128;
    const int wm = (warp >> 1) * 32;
    const int wn = (warp & 1) * 64;
    const int lrow = ((lane >> 3) & 1) * 8 + (lane & 7);
    const int lcol = (lane >> 4) * 8;

    float acc[2][8][4];
#pragma unroll
    for (int i = 0; i < 2; i++)
#pragma unroll
        for (int j = 0; j < 8; j++)
#pragma unroll
            for (int r = 0; r < 4; r++) acc[i][j][r] = 0.0f;

    auto fillA = [&](int buf, int k0) {
#pragma unroll
        for (int it = 0; it < 4; it++) {
            int chunk = tid + it * 256;
            int r = chunk >> 3, c = (chunk & 7) * 8;
            bool p = (m0 + r) < M;
            cp16s(sb + buf * HA_TILE_BYTES + (r * HA_STRIDE + c) * 2,
                  A + (size_t)(p ? m0 + r : 0) * 256 + k0 + c, p);
        }
    };
    auto fillB = [&](int buf, int k0) {
#pragma unroll
        for (int it = 0; it < 4; it++) {
            int chunk = tid + it * 256;
            int pr = chunk >> 5, c2 = (chunk & 31) * 4;
            cp16s(sbB + (buf * HB_TILE2 + pr * HB2_STRIDE + c2) * 4,
                  Bp + (size_t)((k0 >> 1) + pr) * WN + c2, true);
        }
    };

    fillA(0, 0);
    fillB(0, 0);
    cp_commit();

    int buf = 0;
#pragma unroll 1
    for (int i = 0; i < 4; i++) {
        if (i + 1 < 4) {
            fillA(buf ^ 1, (i + 1) * 64);
            fillB(buf ^ 1, (i + 1) * 64);
            cp_commit();
            cp_wait<1>();
        } else {
            cp_wait<0>();
        }
        __syncthreads();

        uint32_t abase = sb + buf * HA_TILE_BYTES;
        const __half2* Bb = hB + buf * HB_TILE2;
#pragma unroll
        for (int kk = 0; kk < 4; kk++) {
            uint32_t af[2][4];
#pragma unroll
            for (int mi = 0; mi < 2; mi++)
                ldsm4(af[mi], abase + ((wm + mi * 16 + lrow) * HA_STRIDE + kk * 16 + lcol) * 2);
            uint32_t bf[8][2];
#pragma unroll
            for (int ni = 0; ni < 8; ni++) {
                const __half2* p = Bb + (kk * 8 + tq) * HB2_STRIDE + wn + ni * 8 + g;
                bf[ni][0] = *(const uint32_t*)(p);
                bf[ni][1] = *(const uint32_t*)(p + 4 * HB2_STRIDE);
            }
#pragma unroll
            for (int mi = 0; mi < 2; mi++)
#pragma unroll
                for (int ni = 0; ni < 8; ni++)
                    mma_f16(acc[mi][ni], af[mi], bf[ni]);
        }
        __syncthreads();
        buf ^= 1;
    }

#pragma unroll
    for (int mi = 0; mi < 2; mi++) {
        int r0 = m0 + wm + mi * 16 + g;
        int r1 = r0 + 8;
#pragma unroll
        for (int ni = 0; ni < 8; ni++) {
            int col = wn + ni * 8 + tq * 2;
            float b0 = __ldg(bias + col);
            float b1 = __ldg(bias + col + 1);
            float v0 = tanhf(acc[mi][ni][0] + b0);
            float v1 = tanhf(acc[mi][ni][1] + b1);
            float v2 = tanhf(acc[mi][ni][2] + b0);
            float v3 = tanhf(acc[mi][ni][3] + b1);
            if (r0 < M) *(__half2*)(Ch + (size_t)r0 * WN + col) = __floats2half2_rn(v0, v1);
            if (r1 < M) *(__half2*)(Ch + (size_t)r1 * WN + col) = __floats2half2_rn(v2, v3);
        }
    }
}

// ---------------- weight packs ---------------------------------------------------
__global__ void wpack_kernel(const float* __restrict__ w1, const float* __restrict__ w2,
                             __half2* __restrict__ w1p, __half2* __restrict__ w2p)
{
    int idx = blockIdx.x * 256 + threadIdx.x;
    int l = idx >> 15;
    int rem = idx & 32767;
    int p = rem >> 8;
    int n = rem & 255;
    size_t base = (size_t)l * 65536 + (size_t)(2 * p) * 256 + n;
    w1p[idx] = __floats2half2_rn(__ldg(w1 + base), __ldg(w1 + base + 256));
    w2p[idx] = __floats2half2_rn(__ldg(w2 + base), __ldg(w2 + base + 256));
}
__global__ void wpack_att_kernel(const float* __restrict__ w, __half2* __restrict__ wp)
{
    int idx = blockIdx.x * 256 + threadIdx.x;
    int p = idx >> 7;
    int n = idx & 127;
    size_t base = (size_t)(2 * p) * 128 + n;
    wp[idx] = __floats2half2_rn(__ldg(w + base), __ldg(w + base + 128));
}

// ===================== mma.sync TF32 GEMM (node embed) ========================
#define GA_STRIDE 36
#define GB_STRIDE 132
#define A_TILE_W (128 * GA_STRIDE)
#define B_TILE_W (32 * GB_STRIDE)
#define GEMM_SMEM_BYTES ((2 * A_TILE_W + 2 * B_TILE_W) * 4)

__device__ __forceinline__ void cp16(float* dst, const float* src, bool pred) {
    cp16s((uint32_t)__cvta_generic_to_shared(dst), src, pred);
}
__device__ __forceinline__ void mma_tf32(float* c, const uint32_t* a, const uint32_t* b) {
    asm volatile(
        "mma.sync.aligned.m16n8k8.row.col.f32.tf32.tf32.f32 "
        "{%0,%1,%2,%3}, {%4,%5,%6,%7}, {%8,%9}, {%0,%1,%2,%3};"
        : "+f"(c[0]), "+f"(c[1]), "+f"(c[2]), "+f"(c[3])
        : "r"(a[0]), "r"(a[1]), "r"(a[2]), "r"(a[3]), "r"(b[0]), "r"(b[1]));
}

__global__ __launch_bounds__(256, 2) void tf32_gemm_h(
    int M, int N, int K,
    const float* __restrict__ A, const float* __restrict__ B,
    const float* __restrict__ bias, __half* __restrict__ Chh)
{
    float* sm = (float*)smemc;
    float* As = sm;
    float* Bs = sm + 2 * A_TILE_W;

    const int tid = threadIdx.x;
    const int warp = tid >> 5;
    const int lane = tid & 31;
    const int g = lane >> 2;
    const int tq = lane & 3;
    const int m0 = blockIdx.y * 128;
    const int n0 = blockIdx.x * 128;
    const int wm = (warp >> 1) * 32;
    const int wn = (warp & 1) * 64;

    float acc[2][8][4];
#pragma unroll
    for (int i = 0; i < 2; i++)
#pragma unroll
        for (int j = 0; j < 8; j++)
#pragma unroll
            for (int r = 0; r < 4; r++) acc[i][j][r] = 0.0f;

    const int arow = tid >> 3;
    const int ac4 = tid & 7;
    const int brow = tid >> 5;
    const int bc4 = tid & 31;
    const int nk = (K + 31) / 32;

    {
#pragma unroll
        for (int it = 0; it < 4; it++) {
            int row = arow + it * 32;
            int gm = m0 + row;
            int gk = ac4 * 4;
            bool p = (gm < M) && (gk < K);
            const float* src = A + (size_t)(p ? gm : 0) * K + (p ? gk : 0);
            cp16(As + row * GA_STRIDE + ac4 * 4, src, p);
        }
#pragma unroll
        for (int it = 0; it < 4; it++) {
            int row = brow + it * 8;
            bool p = (row < K);
            const float* src = B + (size_t)(p ? row : 0) * N + n0 + bc4 * 4;
            cp16(Bs + row * GB_STRIDE + bc4 * 4, src, p);
        }
        cp_commit();
    }

    int buf = 0;
    for (int i = 0; i < nk; i++) {
        if (i + 1 < nk) {
            const int kc = i + 1;
            float* Ad = As + (buf ^ 1) * A_TILE_W;
            float* Bd = Bs + (buf ^ 1) * B_TILE_W;
#pragma unroll
            for (int it = 0; it < 4; it++) {
                int row = arow + it * 32;
                int gm = m0 + row;
                int gk = kc * 32 + ac4 * 4;
                bool p = (gm < M) && (gk < K);
                const float* src = A + (size_t)(p ? gm : 0) * K + (p ? gk : 0);
                cp16(Ad + row * GA_STRIDE + ac4 * 4, src, p);
            }
#pragma unroll
            for (int it = 0; it < 4; it++) {
                int row = brow + it * 8;
                int gk = kc * 32 + row;
                bool p = (gk < K);
                const float* src = B + (size_t)(p ? gk : 0) * N + n0 + bc4 * 4;
                cp16(Bd + row * GB_STRIDE + bc4 * 4, src, p);
            }
            cp_commit();
            cp_wait<1>();
        } else {
            cp_wait<0>();
        }
        __syncthreads();

        const float* Ab = As + buf * A_TILE_W;
        const float* Bb = Bs + buf * B_TILE_W;
#pragma unroll
        for (int kk = 0; kk < 4; kk++) {
            const int k = kk * 8;
            uint32_t af[2][4];
#pragma unroll
            for (int mi = 0; mi < 2; mi++) {
                const float* p = Ab + (wm + mi * 16 + g) * GA_STRIDE + k + tq;
                af[mi][0] = f2tf32(p[0]);
                af[mi][1] = f2tf32(p[8 * GA_STRIDE]);
                af[mi][2] = f2tf32(p[4]);
                af[mi][3] = f2tf32(p[8 * GA_STRIDE + 4]);
            }
            uint32_t bf[8][2];
#pragma unroll
            for (int ni = 0; ni < 8; ni++) {
                const float* p = Bb + (k + tq) * GB_STRIDE + wn + ni * 8 + g;
                bf[ni][0] = f2tf32(p[0]);
                bf[ni][1] = f2tf32(p[4 * GB_STRIDE]);
            }
#pragma unroll
            for (int mi = 0; mi < 2; mi++)
#pragma unroll
                for (int ni = 0; ni < 8; ni++)
                    mma_tf32(acc[mi][ni], af[mi], bf[ni]);
        }
        __syncthreads();
        buf ^= 1;
    }

#pragma unroll
    for (int mi = 0; mi < 2; mi++) {
        int r0 = m0 + wm + mi * 16 + g;
        int r1 = r0 + 8;
#pragma unroll
        for (int ni = 0; ni < 8; ni++) {
            int col = n0 + wn + ni * 8 + tq * 2;
            float b0 = __ldg(bias + col);
            float b1 = __ldg(bias + col + 1);
            if (r0 < M) *(__half2*)(Chh + (size_t)r0 * N + col) =
                __floats2half2_rn(acc[mi][ni][0] + b0, acc[mi][ni][1] + b1);
            if (r1 < M) *(__half2*)(Chh + (size_t)r1 * N + col) =
                __floats2half2_rn(acc[mi][ni][2] + b0, acc[mi][ni][3] + b1);
        }
    }
}

// ---------------- fused edge weights ------------------------------------------
__global__ void wfuse_kernel(const float* __restrict__ edge_w,
                             const float* __restrict__ edge_b,
                             const float* __restrict__ conv_w,
                             const float* __restrict__ conv_b,
                             float* __restrict__ wf)
{
    int layer = blockIdx.x;
    int k = blockIdx.y;
    int c = threadIdx.x;
    const float* cw = conv_w + (size_t)layer * EDIM * HID;
    float s = 0.f;
    if (k < EDGE_F) {
        for (int j = 0; j < EDIM; j++)
            s = fmaf(__ldg(edge_w + k * EDIM + j), __ldg(cw + (size_t)j * HID + c), s);
    } else {
        for (int j = 0; j < EDIM; j++)
            s = fmaf(__ldg(edge_b + j), __ldg(cw + (size_t)j * HID + c), s);
        s += __ldg(conv_b + (size_t)layer * HID + c);
    }
    wf[((size_t)layer * 7 + k) * HID + c] = s;
}

// ---------------- CSR build (parallel scan) -------------------------------------
// deg count (edges) + gstart min (nodes) in one kernel
__global__ void deg_gsmin_kernel(const int* __restrict__ dst,
                                 const int* __restrict__ batch,
                                 int* __restrict__ deg, int* __restrict__ gstart)
{
    int i = blockIdx.x * blockDim.x + threadIdx.x;
    if (i < NEDGES) atomicAdd(&deg[__ldg(dst + i)], 1);
    if (i < NNODES) atomicMin(&gstart[__ldg(batch + i)], i);
}

__global__ void deg_bsum_kernel(const int* __restrict__ deg, int* __restrict__ bsum)
{
    __shared__ int sh[256];
    int i = blockIdx.x * 256 + threadIdx.x;
    sh[threadIdx.x] = (i < NNODES) ? deg[i] : 0;
    __syncthreads();
    for (int o = 128; o > 0; o >>= 1) {
        if (threadIdx.x < o) sh[threadIdx.x] += sh[threadIdx.x + o];
        __syncthreads();
    }
    if (threadIdx.x == 0) bsum[blockIdx.x] = sh[0];
}

__global__ void bscan_kernel(const int* __restrict__ bsum, int* __restrict__ boffs)
{
    __shared__ int sh[512];
    int t = threadIdx.x;
    int mine = (t < NBLKD) ? bsum[t] : 0;
    sh[t] = mine;
    __syncthreads();
    for (int o = 1; o < 512; o <<= 1) {
        int v = (t >= o) ? sh[t - o] : 0;
        __syncthreads();
        sh[t] += v;
        __syncthreads();
    }
    if (t < NBLKD) boffs[t] = sh[t] - mine;
}

__global__ void rowfill_kernel(const int* __restrict__ deg, const int* __restrict__ boffs,
                               int* __restrict__ rowstart, int* __restrict__ cursor)
{
    __shared__ int sh[256];
    int b = blockIdx.x, t = threadIdx.x;
    int i = b * 256 + t;
    int d = (i < NNODES) ? deg[i] : 0;
    sh[t] = d;
    __syncthreads();
    for (int o = 1; o < 256; o <<= 1) {
        int v = (t >= o) ? sh[t - o] : 0;
        __syncthreads();
        sh[t] += v;
        __syncthreads();
    }
    if (i < NNODES) {
        int rs = boffs[b] + sh[t] - d;
        rowstart[i] = rs;
        cursor[i] = rs;
    }
    if (i == NNODES - 1) rowstart[NNODES] = NEDGES;
}

// fill CSR src AND write the CSR-ordered edge attrs directly (eaperm folded in)
__global__ void csr_fill_kernel(const int* __restrict__ src,
                                const int* __restrict__ dst,
                                const float* __restrict__ ea,
                                int* __restrict__ cursor,
                                int* __restrict__ csr_src,
                                float* __restrict__ eap)
{
    int e = blockIdx.x * blockDim.x + threadIdx.x;
    if (e >= NEDGES) return;
    int d = __ldg(dst + e);
    int p = atomicAdd(&cursor[d], 1);
    csr_src[p] = __ldg(src + e);
    const float* ep = ea + (size_t)e * EDGE_F;
    float4 a = make_float4(__ldg(ep), __ldg(ep + 1), __ldg(ep + 2), __ldg(ep + 3));
    float2 b = make_float2(__ldg(ep + 4), __ldg(ep + 5));
    *(float4*)(eap + (size_t)p * 8) = a;
    *(float2*)(eap + (size_t)p * 8 + 4) = b;
}

// ---------------- graph ranges --------------------------------------------------
__global__ void gstart_fix_kernel(int* __restrict__ gstart, float* __restrict__ cnt)
{
    __shared__ int sg[NGRAPH + 1];
    int t = threadIdx.x;
    for (int i = t; i <= NGRAPH; i += 1024) sg[i] = gstart[i];
    __syncthreads();
    if (t == 0) {
        sg[NGRAPH] = NNODES;
        for (int g2 = NGRAPH - 1; g2 >= 0; g2--)
            if (sg[g2] > sg[g2 + 1]) sg[g2] = sg[g2 + 1];
    }
    __syncthreads();
    for (int i = t; i <= NGRAPH; i += 1024) gstart[i] = sg[i];
    for (int i = t; i < NGRAPH; i += 1024)
        cnt[i] = fmaxf((float)(sg[i + 1] - sg[i]), 1.0f);
}

// ---------------- GINE gather (R11 structure: permuted ea + src pipeline) -------
__device__ __forceinline__ float4 h4load(const uint2* hp, int idx) {
    uint2 u = __ldg(hp + idx);
    float2 f0 = __half22float2(*(__half2*)&u.x);
    float2 f1 = __half22float2(*(__half2*)&u.y);
    return make_float4(f0.x, f0.y, f1.x, f1.y);
}

__global__ __launch_bounds__(256) void gine_gather_fused(
    const __half* __restrict__ h,
    const float* __restrict__ eap,
    const int* __restrict__ rowstart,
    const int* __restrict__ csr_src,
    const float* __restrict__ wf,
    const float* __restrict__ eps_ptr,
    __half* __restrict__ aeffh,
    float* __restrict__ stats,
    float* __restrict__ gsum,
    float* __restrict__ gsq)
{
    {
        int gid = blockIdx.x * 256 + threadIdx.x;
        if (gid < 262144) {
            gsum[gid] = 0.f; gsum[gid + 262144] = 0.f;
            gsq[gid] = 0.f;  gsq[gid + 262144] = 0.f;
        }
        if (blockIdx.x == 0) {
            stats[threadIdx.x] = 0.f;
            stats[256 + threadIdx.x] = 0.f;
        }
    }

    const int t = threadIdx.x & 63;
    const int group = (blockIdx.x * blockDim.x + threadIdx.x) >> 6;
    const int ngroups = (gridDim.x * blockDim.x) >> 6;
    const float alpha = 1.0f + __ldg(eps_ptr);

    float4 w[EDGE_F];
#pragma unroll
    for (int k = 0; k < EDGE_F; k++)
        w[k] = __ldg((const float4*)(wf + k * HID) + t);
    float4 bf = __ldg((const float4*)(wf + EDGE_F * HID) + t);

    for (int n = group; n < NNODES; n += ngroups) {
        float4 a = h4load((const uint2*)(h + (size_t)n * HID), t);
        a.x *= alpha; a.y *= alpha; a.z *= alpha; a.w *= alpha;

        int lo = __ldg(rowstart + n), hi = __ldg(rowstart + n + 1);
        int s_next = (lo < hi) ? __ldg(csr_src + lo) : 0;
        for (int j = lo; j < hi; j++) {
            int s_cur = s_next;
            if (j + 1 < hi) s_next = __ldg(csr_src + j + 1);
            float4 e03 = __ldg((const float4*)(eap + (size_t)j * 8));
            float2 e45 = __ldg((const float2*)(eap + (size_t)j * 8 + 4));
            float4 hv = h4load((const uint2*)(h + (size_t)s_cur * HID), t);

            float4 ee = bf;
            ee.x = fmaf(e03.x, w[0].x, ee.x); ee.y = fmaf(e03.x, w[0].y, ee.y);
            ee.z = fmaf(e03.x, w[0].z, ee.z); ee.w = fmaf(e03.x, w[0].w, ee.w);
            ee.x = fmaf(e03.y, w[1].x, ee.x); ee.y = fmaf(e03.y, w[1].y, ee.y);
            ee.z = fmaf(e03.y, w[1].z, ee.z); ee.w = fmaf(e03.y, w[1].w, ee.w);
            ee.x = fmaf(e03.z, w[2].x, ee.x); ee.y = fmaf(e03.z, w[2].y, ee.y);
            ee.z = fmaf(e03.z, w[2].z, ee.z); ee.w = fmaf(e03.z, w[2].w, ee.w);
            ee.x = fmaf(e03.w, w[3].x, ee.x); ee.y = fmaf(e03.w, w[3].y, ee.y);
            ee.z = fmaf(e03.w, w[3].z, ee.z); ee.w = fmaf(e03.w, w[3].w, ee.w);
            ee.x = fmaf(e45.x, w[4].x, ee.x); ee.y = fmaf(e45.x, w[4].y, ee.y);
            ee.z = fmaf(e45.x, w[4].z, ee.z); ee.w = fmaf(e45.x, w[4].w, ee.w);
            ee.x = fmaf(e45.y, w[5].x, ee.x); ee.y = fmaf(e45.y, w[5].y, ee.y);
            ee.z = fmaf(e45.y, w[5].z, ee.z); ee.w = fmaf(e45.y, w[5].w, ee.w);

            a.x += fmaxf(hv.x + ee.x, 0.f);
            a.y += fmaxf(hv.y + ee.y, 0.f);
            a.z += fmaxf(hv.z + ee.z, 0.f);
            a.w += fmaxf(hv.w + ee.w, 0.f);
        }
        __half2* ap = (__half2*)(aeffh + (size_t)n * HID);
        ap[2 * t]     = __floats2half2_rn(a.x, a.y);
        ap[2 * t + 1] = __floats2half2_rn(a.z, a.w);
    }
}

// ---------------- merged attention + pooling (block per graph) -----------------
__global__ void pool_att_kernel(const __half* __restrict__ h,
                                const __half* __restrict__ s1,
                                const float* __restrict__ w2,
                                const float* __restrict__ b2,
                                const int* __restrict__ gstart,
                                const float* __restrict__ cnt,
                                float* __restrict__ out)
{
    __shared__ float swexp[128];
    __shared__ float sw2[128];
    __shared__ float swsum;
    int g = blockIdx.x;
    int t = threadIdx.x;
    int warp = t >> 5, lane = t & 31;
    if (t < 128) sw2[t] = __ldg(w2 + t);
    if (t == 0) swsum = 0.f;
    float b2v = __ldg(b2);
    int lo = gstart[g], hi = gstart[g + 1];
    float s = 0.f, mx = 0.f, att = 0.f;
    __syncthreads();

    for (int c0 = lo; c0 < hi; c0 += 128) {
        int nchunk = min(128, hi - c0);
        for (int j = warp; j < nchunk; j += 8) {
            const __half2* sp = (const __half2*)(s1 + (size_t)(c0 + j) * EDIM);
            float acc = 0.f;
#pragma unroll
            for (int k = lane; k < 64; k += 32) {
                float2 f = __half22float2(__ldg(sp + k));
                acc = fmaf(f.x, sw2[2 * k], acc);
                acc = fmaf(f.y, sw2[2 * k + 1], acc);
            }
#pragma unroll
            for (int o = 16; o > 0; o >>= 1) acc += __shfl_down_sync(0xffffffffu, acc, o);
            if (lane == 0) swexp[j] = expf(acc + b2v);
        }
        __syncthreads();
        if (t < 32) {
            float wv = 0.f;
            for (int j = t; j < nchunk; j += 32) wv += swexp[j];
#pragma unroll
            for (int o = 16; o > 0; o >>= 1) wv += __shfl_down_sync(0xffffffffu, wv, o);
            if (t == 0) swsum += wv;
        }
        for (int j = 0; j < nchunk; j++) {
            float v = __half2float(__ldg(h + (size_t)(c0 + j) * HID + t));
            s += v;
            mx = fmaxf(mx, v);
            att = fmaf(v, swexp[j], att);
        }
        __syncthreads();
    }
    float* og = out + (size_t)g * (3 * HID);
    og[t] = s / cnt[g];
    og[HID + t] = mx;
    og[2 * HID + t] = att / (swsum + 1e-8f);
}

// ---------------- host launch --------------------------------------------------------
extern "C" void kernel_launch(void* const* d_in, const int* in_sizes, int n_in,
                              void* d_out, int out_size)
{
    const float* x         = (const float*)d_in[0];
    const float* edge_attr = (const float*)d_in[1];
    const float* node_w    = (const float*)d_in[2];
    const float* node_b    = (const float*)d_in[3];
    const float* edge_w    = (const float*)d_in[4];
    const float* edge_b    = (const float*)d_in[5];
    const float* conv_w    = (const float*)d_in[6];
    const float* conv_b    = (const float*)d_in[7];
    const float* mlp_w1    = (const float*)d_in[8];
    const float* mlp_b1    = (const float*)d_in[9];
    const float* mlp_w2    = (const float*)d_in[10];
    const float* mlp_b2    = (const float*)d_in[11];
    const float* eps       = (const float*)d_in[12];
    const float* bn_gamma  = (const float*)d_in[13];
    const float* bn_beta   = (const float*)d_in[14];
    const float* att_w1    = (const float*)d_in[15];
    const float* att_b1    = (const float*)d_in[16];
    const float* att_w2    = (const float*)d_in[17];
    const float* att_b2    = (const float*)d_in[18];
    const int*   edge_index= (const int*)d_in[19];
    const int*   batch     = (const int*)d_in[20];
    float* out = (float*)d_out;
    (void)bn_beta;   // cancels exactly under PairNorm centering

    const int* src = edge_index;
    const int* dst = edge_index + NEDGES;

    const int HG_SMEM_128 = 2 * HA_TILE_BYTES + 2 * 32 * (128 + 4) * 4;

    cudaFuncSetAttribute(tf32_gemm_h, cudaFuncAttributeMaxDynamicSharedMemorySize, GEMM_SMEM_BYTES);
    cudaFuncSetAttribute(fused_mlp, cudaFuncAttributeMaxDynamicSharedMemorySize, FUSED_SMEM);
    cudaFuncSetAttribute(hgemm_att, cudaFuncAttributeMaxDynamicSharedMemorySize, HG_SMEM_128);

    float *p_stats, *p_gsum, *p_gsq, *p_cnt, *p_wf, *p_eap;
    __half *p_hh0, *p_hh1, *p_zh, *p_aeffh, *p_s1h;
    __half2 *p_w1p, *p_w2p, *p_w1a;
    int *p_deg, *p_bsum, *p_boffs, *p_rowstart, *p_cursor, *p_csrc, *p_gstart;
    cudaGetSymbolAddress((void**)&p_hh0, g_hh0);
    cudaGetSymbolAddress((void**)&p_hh1, g_hh1);
    cudaGetSymbolAddress((void**)&p_zh, g_zh);
    cudaGetSymbolAddress((void**)&p_aeffh, g_aeffh);
    cudaGetSymbolAddress((void**)&p_s1h, g_s1h);
    cudaGetSymbolAddress((void**)&p_w1p, g_w1p);
    cudaGetSymbolAddress((void**)&p_w2p, g_w2p);
    cudaGetSymbolAddress((void**)&p_w1a, g_w1a);
    cudaGetSymbolAddress((void**)&p_eap, g_eap);
    cudaGetSymbolAddress((void**)&p_stats, g_stats);
    cudaGetSymbolAddress((void**)&p_gsum, g_gsum);
    cudaGetSymbolAddress((void**)&p_gsq, g_gsq);
    cudaGetSymbolAddress((void**)&p_cnt, g_cnt);
    cudaGetSymbolAddress((void**)&p_wf, g_wf);
    cudaGetSymbolAddress((void**)&p_deg, g_deg);
    cudaGetSymbolAddress((void**)&p_bsum, g_bsum);
    cudaGetSymbolAddress((void**)&p_boffs, g_boffs);
    cudaGetSymbolAddress((void**)&p_rowstart, g_rowstart);
    cudaGetSymbolAddress((void**)&p_cursor, g_cursor);
    cudaGetSymbolAddress((void**)&p_csrc, g_csr_src);
    cudaGetSymbolAddress((void**)&p_gstart, g_gstart);

    // ----- CSR build (parallel scan) + graph ranges, merged where possible
    cudaMemsetAsync(p_deg, 0, NNODES * sizeof(int));
    cudaMemsetAsync(p_gstart, 0x7F, (NGRAPH + 1) * sizeof(int));
    deg_gsmin_kernel<<<(NEDGES + 255) / 256, 256>>>(dst, batch, p_deg, p_gstart);
    deg_bsum_kernel<<<NBLKD, 256>>>(p_deg, p_bsum);
    bscan_kernel<<<1, 512>>>(p_bsum, p_boffs);
    rowfill_kernel<<<NBLKD, 256>>>(p_deg, p_boffs, p_rowstart, p_cursor);
    csr_fill_kernel<<<(NEDGES + 255) / 256, 256>>>(src, dst, edge_attr, p_cursor, p_csrc, p_eap);
    gstart_fix_kernel<<<1, 1024>>>(p_gstart, p_cnt);

    // ----- weight prep
    wfuse_kernel<<<dim3(NLAYER, 7), HID>>>(edge_w, edge_b, conv_w, conv_b, p_wf);
    wpack_kernel<<<(NLAYER * 128 * 256) / 256, 256>>>(mlp_w1, mlp_w2, p_w1p, p_w2p);
    wpack_att_kernel<<<(128 * 128) / 256, 256>>>(att_w1, p_w1a);

    // ----- node embedding (tf32, half output)
    {
        dim3 grid(HID / 128, (NNODES + 127) / 128);
        tf32_gemm_h<<<grid, 256, GEMM_SMEM_BYTES>>>(NNODES, HID, NODE_F, x, node_w,
                                                    node_b, p_hh0);
    }

    __half* h_cur = p_hh0;
    __half* h_nxt = p_hh1;
    const int mgrid = (NNODES + 127) / 128;

    for (int i = 0; i < NLAYER; i++) {
        gine_gather_fused<<<2048, 256>>>(
            h_cur, p_eap, p_rowstart, p_csrc,
            p_wf + (size_t)i * 7 * HID, eps + i, p_aeffh, p_stats, p_gsum, p_gsq);

        fused_mlp<<<mgrid, 512, FUSED_SMEM>>>(
            NNODES, p_aeffh,
            p_w1p + (size_t)i * 32768, p_w2p + (size_t)i * 32768,
            mlp_b1 + (size_t)i * HID, mlp_b2 + (size_t)i * HID,
            batch, p_gsum, p_gsq, p_stats, p_zh);

        msq_norm_kernel<<<NGRAPH, HID>>>(p_stats, bn_gamma + (size_t)i * HID,
                                         p_cnt, p_gsum, p_gsq, p_gstart, p_zh, h_nxt);

        __half* t = h_cur; h_cur = h_nxt; h_nxt = t;
    }

    // attention hidden: s1 = tanh(h @ att_w1 + att_b1)
    {
        dim3 agrid(1, (NNODES + 127) / 128);
        hgemm_att<<<agrid, 256, HG_SMEM_128>>>(NNODES, h_cur, p_w1a, att_b1, p_s1h);
    }

    // merged attention-score + pooling
    pool_att_kernel<<<NGRAPH, HID>>>(h_cur, p_s1h, att_w2, att_b2, p_gstart, p_cnt, out);

    (void)in_sizes; (void)n_in; (void)out_size;
}

// round 15
// speedup vs baseline: 1.2036x; 1.0232x over previous
#include <cuda_runtime.h>
#include <cuda_fp16.h>
#include <math.h>
#include <stdint.h>

#define NNODES 100000
#define NEDGES 320000
#define NGRAPH 2048
#define HID    256
#define EDIM   128
#define NODE_F 48
#define EDGE_F 6
#define NLAYER 8
#define NBLKD  ((NNODES + 255) / 256)   // 391

// ---------------- scratch (device globals) ----------------------------------
__device__ __half  g_hh0[(size_t)NNODES * HID];
__device__ __half  g_hh1[(size_t)NNODES * HID];
__device__ __half  g_zh [(size_t)NNODES * HID];
__device__ __half  g_aeffh[(size_t)NNODES * HID];
__device__ __half  g_s1h [(size_t)NNODES * EDIM];
__device__ __half2 g_w1p[(size_t)NLAYER * (HID / 2) * HID];
__device__ __half2 g_w2p[(size_t)NLAYER * (HID / 2) * HID];
__device__ __half2 g_w1a[(size_t)(HID / 2) * EDIM];
__device__ float   g_eap[(size_t)NEDGES * 8];     // CSR-ordered edge attrs (padded)
__device__ float   g_stats[2 * HID];
__device__ float   g_gsum[(size_t)NGRAPH * HID];
__device__ float   g_gsq [(size_t)NGRAPH * HID];
__device__ float   g_cnt [NGRAPH];
__device__ float   g_wf  [(size_t)NLAYER * 7 * HID];
__device__ int     g_deg [NNODES];
__device__ int     g_bsum[NBLKD];
__device__ int     g_boffs[NBLKD];
__device__ int     g_rowstart[NNODES + 1];
__device__ int     g_cursor[NNODES];
__device__ int     g_csr_src[NEDGES];
__device__ int     g_gstart[NGRAPH + 1];

// ---------------- common helpers ---------------------------------------------
__device__ __forceinline__ uint32_t f2tf32(float x) {
    uint32_t r;
    asm volatile("cvt.rna.tf32.f32 %0, %1;" : "=r"(r) : "f"(x));
    return r;
}
__device__ __forceinline__ void cp16s(uint32_t d, const void* src, bool pred) {
    int sz = pred ? 16 : 0;
    asm volatile("cp.async.cg.shared.global [%0], [%1], 16, %2;" :: "r"(d), "l"(src), "r"(sz));
}
__device__ __forceinline__ void cp_commit() { asm volatile("cp.async.commit_group;"); }
template <int Np>
__device__ __forceinline__ void cp_wait() { asm volatile("cp.async.wait_group %0;" :: "n"(Np)); }
__device__ __forceinline__ void mma_f16(float* c, const uint32_t* a, const uint32_t* b) {
    asm volatile(
        "mma.sync.aligned.m16n8k16.row.col.f32.f16.f16.f32 "
        "{%0,%1,%2,%3}, {%4,%5,%6,%7}, {%8,%9}, {%0,%1,%2,%3};"
        : "+f"(c[0]), "+f"(c[1]), "+f"(c[2]), "+f"(c[3])
        : "r"(a[0]), "r"(a[1]), "r"(a[2]), "r"(a[3]), "r"(b[0]), "r"(b[1]));
}
__device__ __forceinline__ void ldsm4(uint32_t* r, uint32_t addr) {
    asm volatile("ldmatrix.sync.aligned.m8n8.x4.shared.b16 {%0,%1,%2,%3}, [%4];"
                 : "=r"(r[0]), "=r"(r[1]), "=r"(r[2]), "=r"(r[3]) : "r"(addr));
}

extern __shared__ char smemc[];

// ===================== fused MLP + stats ========================================
#define FA_STRIDE 72
#define FA_TILE_BYTES (128 * FA_STRIDE * 2)
#define FB2_STRIDE 260
#define FB_TILE2 (32 * FB2_STRIDE)
#define FTMP_STRIDE 264
#define OFF_B (2 * FA_TILE_BYTES)
#define OFF_TMP (OFF_B + 2 * FB_TILE2 * 4)
#define FUSED_SMEM (OFF_TMP + 128 * FTMP_STRIDE * 2)   // 171008

__global__ __launch_bounds__(512, 1) void fused_mlp(
    int M, const __half* __restrict__ A,
    const __half2* __restrict__ W1p, const __half2* __restrict__ W2p,
    const float* __restrict__ b1, const float* __restrict__ b2,
    const int* __restrict__ batchp,
    float* __restrict__ gsum, float* __restrict__ gsq, float* __restrict__ stats,
    __half* __restrict__ Z)
{
    uint32_t sb = (uint32_t)__cvta_generic_to_shared(smemc);
    const __half2* hB = (const __half2*)(smemc + OFF_B);
    __half* tmp = (__half*)(smemc + OFF_TMP);
    uint32_t sbT = sb + OFF_TMP;

    const int tid = threadIdx.x;
    const int warp = tid >> 5;
    const int lane = tid & 31;
    const int g = lane >> 2;
    const int tq = lane & 3;
    const int m0 = blockIdx.x * 128;
    const int wm = (warp & 3) * 32;
    const int wn = (warp >> 2) * 64;
    const int lrow = ((lane >> 3) & 1) * 8 + (lane & 7);
    const int lcol = (lane >> 4) * 8;

    float acc[2][8][4];
#pragma unroll
    for (int i = 0; i < 2; i++)
#pragma unroll
        for (int j = 0; j < 8; j++)
#pragma unroll
            for (int r = 0; r < 4; r++) acc[i][j][r] = 0.0f;

    auto fillA = [&](int buf, int k0) {
#pragma unroll
        for (int it = 0; it < 2; it++) {
            int chunk = tid + it * 512;
            int r = chunk >> 3, c = (chunk & 7) * 8;
            bool p = (m0 + r) < M;
            cp16s(sb + buf * FA_TILE_BYTES + (r * FA_STRIDE + c) * 2,
                  A + (size_t)(p ? m0 + r : 0) * 256 + k0 + c, p);
        }
    };
    auto fillB = [&](int buf, int k0, const __half2* W) {
#pragma unroll
        for (int it = 0; it < 4; it++) {
            int chunk = tid + it * 512;
            int pr = chunk >> 6, c2 = (chunk & 63) * 4;
            cp16s(sb + OFF_B + (buf * FB_TILE2 + pr * FB2_STRIDE + c2) * 4,
                  W + (size_t)((k0 >> 1) + pr) * 256 + c2, true);
        }
    };

    // phase 1: acc = A @ W1
    fillA(0, 0);
    fillB(0, 0, W1p);
    cp_commit();

    int buf = 0;
#pragma unroll 1
    for (int i = 0; i < 4; i++) {
        if (i < 3) {
            fillA(buf ^ 1, (i + 1) * 64);
            fillB(buf ^ 1, (i + 1) * 64, W1p);
        } else {
            fillB(buf ^ 1, 0, W2p);
        }
        cp_commit();
        cp_wait<1>();
        __syncthreads();

        uint32_t abase = sb + buf * FA_TILE_BYTES;
        const __half2* Bb = hB + buf * FB_TILE2;
#pragma unroll
        for (int kk = 0; kk < 4; kk++) {
            uint32_t af[2][4];
#pragma unroll
            for (int mi = 0; mi < 2; mi++)
                ldsm4(af[mi], abase + ((wm + mi * 16 + lrow) * FA_STRIDE + kk * 16 + lcol) * 2);
            uint32_t bf[8][2];
#pragma unroll
            for (int ni = 0; ni < 8; ni++) {
                const __half2* p = Bb + (kk * 8 + tq) * FB2_STRIDE + wn + ni * 8 + g;
                bf[ni][0] = *(const uint32_t*)(p);
                bf[ni][1] = *(const uint32_t*)(p + 4 * FB2_STRIDE);
            }
#pragma unroll
            for (int mi = 0; mi < 2; mi++)
#pragma unroll
                for (int ni = 0; ni < 8; ni++)
                    mma_f16(acc[mi][ni], af[mi], bf[ni]);
        }
        __syncthreads();
        buf ^= 1;
    }

    if (tid < 128)
        ((int*)smemc)[tid] = (m0 + tid < M) ? __ldg(batchp + m0 + tid) : 0;

    // phase 1 epilogue: tmp = relu(acc + b1)
#pragma unroll
    for (int mi = 0; mi < 2; mi++) {
        int r0 = wm + mi * 16 + g;
        int r1 = r0 + 8;
#pragma unroll
        for (int ni = 0; ni < 8; ni++) {
            int col = wn + ni * 8 + tq * 2;
            float c0 = __ldg(b1 + col);
            float c1 = __ldg(b1 + col + 1);
            float v0 = fmaxf(acc[mi][ni][0] + c0, 0.f);
            float v1 = fmaxf(acc[mi][ni][1] + c1, 0.f);
            float v2 = fmaxf(acc[mi][ni][2] + c0, 0.f);
            float v3 = fmaxf(acc[mi][ni][3] + c1, 0.f);
            *(__half2*)(tmp + r0 * FTMP_STRIDE + col) = __floats2half2_rn(v0, v1);
            *(__half2*)(tmp + r1 * FTMP_STRIDE + col) = __floats2half2_rn(v2, v3);
            acc[mi][ni][0] = 0.f; acc[mi][ni][1] = 0.f;
            acc[mi][ni][2] = 0.f; acc[mi][ni][3] = 0.f;
        }
    }

    // phase 2: acc = tmp @ W2
#pragma unroll 1
    for (int i = 0; i < 4; i++) {
        if (i < 3) {
            fillB(buf ^ 1, (i + 1) * 64, W2p);
            cp_commit();
            cp_wait<1>();
        } else {
            cp_wait<0>();
        }
        __syncthreads();

        const __half2* Bb = hB + buf * FB_TILE2;
#pragma unroll
        for (int kk = 0; kk < 4; kk++) {
            uint32_t af[2][4];
#pragma unroll
            for (int mi = 0; mi < 2; mi++)
                ldsm4(af[mi], sbT + ((wm + mi * 16 + lrow) * FTMP_STRIDE + i * 64 + kk * 16 + lcol) * 2);
            uint32_t bf[8][2];
#pragma unroll
            for (int ni = 0; ni < 8; ni++) {
                const __half2* p = Bb + (kk * 8 + tq) * FB2_STRIDE + wn + ni * 8 + g;
                bf[ni][0] = *(const uint32_t*)(p);
                bf[ni][1] = *(const uint32_t*)(p + 4 * FB2_STRIDE);
            }
#pragma unroll
            for (int mi = 0; mi < 2; mi++)
#pragma unroll
                for (int ni = 0; ni < 8; ni++)
                    mma_f16(acc[mi][ni], af[mi], bf[ni]);
        }
        __syncthreads();
        buf ^= 1;
    }

    // phase 2 epilogue: Z(global) + z(tmp smem)
#pragma unroll
    for (int mi = 0; mi < 2; mi++) {
        int rr0 = wm + mi * 16 + g;
        int rr1 = rr0 + 8;
        int r0 = m0 + rr0;
        int r1 = m0 + rr1;
#pragma unroll
        for (int ni = 0; ni < 8; ni++) {
            int col = wn + ni * 8 + tq * 2;
            float c0 = __ldg(b2 + col);
            float c1 = __ldg(b2 + col + 1);
            __half2 z0 = __floats2half2_rn(acc[mi][ni][0] + c0, acc[mi][ni][1] + c1);
            __half2 z1 = __floats2half2_rn(acc[mi][ni][2] + c0, acc[mi][ni][3] + c1);
            *(__half2*)(tmp + rr0 * FTMP_STRIDE + col) = z0;
            *(__half2*)(tmp + rr1 * FTMP_STRIDE + col) = z1;
            if (r0 < M) *(__half2*)(Z + (size_t)r0 * 256 + col) = z0;
            if (r1 < M) *(__half2*)(Z + (size_t)r1 * 256 + col) = z1;
        }
    }
    __syncthreads();

    // phase 3: per-graph + chip stats from smem z
    {
        const int c = tid & 255;
        const int rbeg = (tid >> 8) * 64;
        const int* sbatch = (const int*)smemc;
        float ts = 0.f, tqs = 0.f;
        int curg = -1;
        float s = 0.f, q = 0.f;
        for (int r = rbeg; r < rbeg + 64; r++) {
            if (m0 + r >= M) break;
            int gg = sbatch[r];
            if (gg != curg) {
                if (curg >= 0) {
                    atomicAdd(gsum + (size_t)curg * 256 + c, s);
                    atomicAdd(gsq + (size_t)curg * 256 + c, q);
                }
                curg = gg; s = 0.f; q = 0.f;
            }
            float v = __half2float(tmp[r * FTMP_STRIDE + c]);
            s += v; q = fmaf(v, v, q);
            ts += v; tqs = fmaf(v, v, tqs);
        }
        if (curg >= 0) {
            atomicAdd(gsum + (size_t)curg * 256 + c, s);
            atomicAdd(gsq + (size_t)curg * 256 + c, q);
        }
        atomicAdd(stats + c, ts);
        atomicAdd(stats + 256 + c, tqs);
    }
}

// ===================== merged msq + normalize (block per graph, half2) =========
__global__ void msq_norm_kernel(const float* __restrict__ stats,
                                const float* __restrict__ gamma,
                                const float* __restrict__ cnt,
                                const float* __restrict__ gsum,
                                const float* __restrict__ gsq,
                                const int* __restrict__ gstart,
                                const __half* __restrict__ zh,
                                __half* __restrict__ hout)
{
    __shared__ float red[HID];
    __shared__ float sacs[HID];
    __shared__ float sm[HID];
    int gb = blockIdx.x;
    int c = threadIdx.x;
    const float invN = 1.0f / (float)NNODES;
    float mu = __ldg(stats + c) * invN;
    float var = __ldg(stats + HID + c) * invN - mu * mu;
    float ac = __ldg(gamma + c) * rsqrtf(var + 1e-5f);
    float cg = cnt[gb];
    size_t gi = (size_t)gb * HID + c;
    float S = gsum[gi], Q = gsq[gi];
    float m = S / cg;
    sm[c] = m;
    red[c] = ac * ac * (Q - cg * m * m);
    __syncthreads();
    for (int o = HID / 2; o > 0; o >>= 1) {
        if (c < o) red[c] += red[c + o];
        __syncthreads();
    }
    float sc = rsqrtf(1e-5f + red[0] / cg);
    sacs[c] = ac * sc;
    __syncthreads();

    // half2 streaming: thread t -> channel pair 2*(t&127), row n + (t>>7); 2 rows/iter
    int c2 = (c & 127) * 2;
    int rr = c >> 7;
    float acs0 = sacs[c2],  m0 = sm[c2];
    float acs1 = sacs[c2 + 1], m1 = sm[c2 + 1];
    int lo = gstart[gb], hi = gstart[gb + 1];
    for (int n = lo + rr; n < hi; n += 2) {
        size_t i = (size_t)n * HID + c2;
        float2 f = __half22float2(*(const __half2*)(zh + i));
        float v0 = fmaxf(acs0 * (f.x - m0), 0.f);
        float v1 = fmaxf(acs1 * (f.y - m1), 0.f);
        *(__half2*)(hout + i) = __floats2half2_rn(v0, v1);
    }
}

// ===================== fp16 GEMM (attention, tanh) =============================
#define HA_STRIDE 72
#define HA_TILE_BYTES (128 * HA_STRIDE * 2)

__global__ __launch_bounds__(256, 2) void hgemm_att(
    int M, const __half* __restrict__ A, const __half2* __restrict__ Bp,
    const float* __restrict__ bias, __half* __restrict__ Ch)
{
    constexpr int WN = 128;
    constexpr int HB2_STRIDE = WN + 4;
    constexpr int HB_TILE2 = 32 * HB2_STRIDE;
    const __half2* hB = (const __half2*)(smemc + 2 * HA_TILE_BYTES);
    uint32_t sb = (uint32_t)__cvta_generic_to_shared(smemc);
    uint32_t sbB = sb + 2 * HA_TILE_BYTES;

    const int tid = threadIdx.x;
    const int warp = tid >> 5;
    const int lane = tid & 31;
    const int g = lane >> 2;
    const int tq = lane & 3;
    const int m0 = blockIdx.y * 128;
    const int wm = (warp >> 1) * 32;
    const int wn = (warp & 1) * 64;
    const int lrow = ((lane >> 3) & 1) * 8 + (lane & 7);
    const int lcol = (lane >> 4) * 8;

    float acc[2][8][4];
#pragma unroll
    for (int i = 0; i < 2; i++)
#pragma unroll
        for (int j = 0; j < 8; j++)
#pragma unroll
            for (int r = 0; r < 4; r++) acc[i][j][r] = 0.0f;

    auto fillA = [&](int buf, int k0) {
#pragma unroll
        for (int it = 0; it < 4; it++) {
            int chunk = tid + it * 256;
            int r = chunk >> 3, c = (chunk & 7) * 8;
            bool p = (m0 + r) < M;
            cp16s(sb + buf * HA_TILE_BYTES + (r * HA_STRIDE + c) * 2,
                  A + (size_t)(p ? m0 + r : 0) * 256 + k0 + c, p);
        }
    };
    auto fillB = [&](int buf, int k0) {
#pragma unroll
        for (int it = 0; it < 4; it++) {
            int chunk = tid + it * 256;
            int pr = chunk >> 5, c2 = (chunk & 31) * 4;
            cp16s(sbB + (buf * HB_TILE2 + pr * HB2_STRIDE + c2) * 4,
                  Bp + (size_t)((k0 >> 1) + pr) * WN + c2, true);
        }
    };

    fillA(0, 0);
    fillB(0, 0);
    cp_commit();

    int buf = 0;
#pragma unroll 1
    for (int i = 0; i < 4; i++) {
        if (i + 1 < 4) {
            fillA(buf ^ 1, (i + 1) * 64);
            fillB(buf ^ 1, (i + 1) * 64);
            cp_commit();
            cp_wait<1>();
        } else {
            cp_wait<0>();
        }
        __syncthreads();

        uint32_t abase = sb + buf * HA_TILE_BYTES;
        const __half2* Bb = hB + buf * HB_TILE2;
#pragma unroll
        for (int kk = 0; kk < 4; kk++) {
            uint32_t af[2][4];
#pragma unroll
            for (int mi = 0; mi < 2; mi++)
                ldsm4(af[mi], abase + ((wm + mi * 16 + lrow) * HA_STRIDE + kk * 16 + lcol) * 2);
            uint32_t bf[8][2];
#pragma unroll
            for (int ni = 0; ni < 8; ni++) {
                const __half2* p = Bb + (kk * 8 + tq) * HB2_STRIDE + wn + ni * 8 + g;
                bf[ni][0] = *(const uint32_t*)(p);
                bf[ni][1] = *(const uint32_t*)(p + 4 * HB2_STRIDE);
            }
#pragma unroll
            for (int mi = 0; mi < 2; mi++)
#pragma unroll
                for (int ni = 0; ni < 8; ni++)
                    mma_f16(acc[mi][ni], af[mi], bf[ni]);
        }
        __syncthreads();
        buf ^= 1;
    }

#pragma unroll
    for (int mi = 0; mi < 2; mi++) {
        int r0 = m0 + wm + mi * 16 + g;
        int r1 = r0 + 8;
#pragma unroll
        for (int ni = 0; ni < 8; ni++) {
            int col = wn + ni * 8 + tq * 2;
            float b0 = __ldg(bias + col);
            float b1 = __ldg(bias + col + 1);
            float v0 = tanhf(acc[mi][ni][0] + b0);
            float v1 = tanhf(acc[mi][ni][1] + b1);
            float v2 = tanhf(acc[mi][ni][2] + b0);
            float v3 = tanhf(acc[mi][ni][3] + b1);
            if (r0 < M) *(__half2*)(Ch + (size_t)r0 * WN + col) = __floats2half2_rn(v0, v1);
            if (r1 < M) *(__half2*)(Ch + (size_t)r1 * WN + col) = __floats2half2_rn(v2, v3);
        }
    }
}

// ---------------- weight packs ---------------------------------------------------
__global__ void wpack_kernel(const float* __restrict__ w1, const float* __restrict__ w2,
                             __half2* __restrict__ w1p, __half2* __restrict__ w2p)
{
    int idx = blockIdx.x * 256 + threadIdx.x;
    int l = idx >> 15;
    int rem = idx & 32767;
    int p = rem >> 8;
    int n = rem & 255;
    size_t base = (size_t)l * 65536 + (size_t)(2 * p) * 256 + n;
    w1p[idx] = __floats2half2_rn(__ldg(w1 + base), __ldg(w1 + base + 256));
    w2p[idx] = __floats2half2_rn(__ldg(w2 + base), __ldg(w2 + base + 256));
}
__global__ void wpack_att_kernel(const float* __restrict__ w, __half2* __restrict__ wp)
{
    int idx = blockIdx.x * 256 + threadIdx.x;
    int p = idx >> 7;
    int n = idx & 127;
    size_t base = (size_t)(2 * p) * 128 + n;
    wp[idx] = __floats2half2_rn(__ldg(w + base), __ldg(w + base + 128));
}

// ===================== mma.sync TF32 GEMM (node embed) ========================
#define GA_STRIDE 36
#define GB_STRIDE 132
#define A_TILE_W (128 * GA_STRIDE)
#define B_TILE_W (32 * GB_STRIDE)
#define GEMM_SMEM_BYTES ((2 * A_TILE_W + 2 * B_TILE_W) * 4)

__device__ __forceinline__ void cp16(float* dst, const float* src, bool pred) {
    cp16s((uint32_t)__cvta_generic_to_shared(dst), src, pred);
}
__device__ __forceinline__ void mma_tf32(float* c, const uint32_t* a, const uint32_t* b) {
    asm volatile(
        "mma.sync.aligned.m16n8k8.row.col.f32.tf32.tf32.f32 "
        "{%0,%1,%2,%3}, {%4,%5,%6,%7}, {%8,%9}, {%0,%1,%2,%3};"
        : "+f"(c[0]), "+f"(c[1]), "+f"(c[2]), "+f"(c[3])
        : "r"(a[0]), "r"(a[1]), "r"(a[2]), "r"(a[3]), "r"(b[0]), "r"(b[1]));
}

__global__ __launch_bounds__(256, 2) void tf32_gemm_h(
    int M, int N, int K,
    const float* __restrict__ A, const float* __restrict__ B,
    const float* __restrict__ bias, __half* __restrict__ Chh)
{
    float* sm = (float*)smemc;
    float* As = sm;
    float* Bs = sm + 2 * A_TILE_W;

    const int tid = threadIdx.x;
    const int warp = tid >> 5;
    const int lane = tid & 31;
    const int g = lane >> 2;
    const int tq = lane & 3;
    const int m0 = blockIdx.y * 128;
    const int n0 = blockIdx.x * 128;
    const int wm = (warp >> 1) * 32;
    const int wn = (warp & 1) * 64;

    float acc[2][8][4];
#pragma unroll
    for (int i = 0; i < 2; i++)
#pragma unroll
        for (int j = 0; j < 8; j++)
#pragma unroll
            for (int r = 0; r < 4; r++) acc[i][j][r] = 0.0f;

    const int arow = tid >> 3;
    const int ac4 = tid & 7;
    const int brow = tid >> 5;
    const int bc4 = tid & 31;
    const int nk = (K + 31) / 32;

    {
#pragma unroll
        for (int it = 0; it < 4; it++) {
            int row = arow + it * 32;
            int gm = m0 + row;
            int gk = ac4 * 4;
            bool p = (gm < M) && (gk < K);
            const float* src = A + (size_t)(p ? gm : 0) * K + (p ? gk : 0);
            cp16(As + row * GA_STRIDE + ac4 * 4, src, p);
        }
#pragma unroll
        for (int it = 0; it < 4; it++) {
            int row = brow + it * 8;
            bool p = (row < K);
            const float* src = B + (size_t)(p ? row : 0) * N + n0 + bc4 * 4;
            cp16(Bs + row * GB_STRIDE + bc4 * 4, src, p);
        }
        cp_commit();
    }

    int buf = 0;
    for (int i = 0; i < nk; i++) {
        if (i + 1 < nk) {
            const int kc = i + 1;
            float* Ad = As + (buf ^ 1) * A_TILE_W;
            float* Bd = Bs + (buf ^ 1) * B_TILE_W;
#pragma unroll
            for (int it = 0; it < 4; it++) {
                int row = arow + it * 32;
                int gm = m0 + row;
                int gk = kc * 32 + ac4 * 4;
                bool p = (gm < M) && (gk < K);
                const float* src = A + (size_t)(p ? gm : 0) * K + (p ? gk : 0);
                cp16(Ad + row * GA_STRIDE + ac4 * 4, src, p);
            }
#pragma unroll
            for (int it = 0; it < 4; it++) {
                int row = brow + it * 8;
                int gk = kc * 32 + row;
                bool p = (gk < K);
                const float* src = B + (size_t)(p ? gk : 0) * N + n0 + bc4 * 4;
                cp16(Bd + row * GB_STRIDE + bc4 * 4, src, p);
            }
            cp_commit();
            cp_wait<1>();
        } else {
            cp_wait<0>();
        }
        __syncthreads();

        const float* Ab = As + buf * A_TILE_W;
        const float* Bb = Bs + buf * B_TILE_W;
#pragma unroll
        for (int kk = 0; kk < 4; kk++) {
            const int k = kk * 8;
            uint32_t af[2][4];
#pragma unroll
            for (int mi = 0; mi < 2; mi++) {
                const float* p = Ab + (wm + mi * 16 + g) * GA_STRIDE + k + tq;
                af[mi][0] = f2tf32(p[0]);
                af[mi][1] = f2tf32(p[8 * GA_STRIDE]);
                af[mi][2] = f2tf32(p[4]);
                af[mi][3] = f2tf32(p[8 * GA_STRIDE + 4]);
            }
            uint32_t bf[8][2];
#pragma unroll
            for (int ni = 0; ni < 8; ni++) {
                const float* p = Bb + (k + tq) * GB_STRIDE + wn + ni * 8 + g;
                bf[ni][0] = f2tf32(p[0]);
                bf[ni][1] = f2tf32(p[4 * GB_STRIDE]);
            }
#pragma unroll
            for (int mi = 0; mi < 2; mi++)
#pragma unroll
                for (int ni = 0; ni < 8; ni++)
                    mma_tf32(acc[mi][ni], af[mi], bf[ni]);
        }
        __syncthreads();
        buf ^= 1;
    }

#pragma unroll
    for (int mi = 0; mi < 2; mi++) {
        int r0 = m0 + wm + mi * 16 + g;
        int r1 = r0 + 8;
#pragma unroll
        for (int ni = 0; ni < 8; ni++) {
            int col = n0 + wn + ni * 8 + tq * 2;
            float b0 = __ldg(bias + col);
            float b1 = __ldg(bias + col + 1);
            if (r0 < M) *(__half2*)(Chh + (size_t)r0 * N + col) =
                __floats2half2_rn(acc[mi][ni][0] + b0, acc[mi][ni][1] + b1);
            if (r1 < M) *(__half2*)(Chh + (size_t)r1 * N + col) =
                __floats2half2_rn(acc[mi][ni][2] + b0, acc[mi][ni][3] + b1);
        }
    }
}

// ---------------- fused edge weights ------------------------------------------
__global__ void wfuse_kernel(const float* __restrict__ edge_w,
                             const float* __restrict__ edge_b,
                             const float* __restrict__ conv_w,
                             const float* __restrict__ conv_b,
                             float* __restrict__ wf)
{
    int layer = blockIdx.x;
    int k = blockIdx.y;
    int c = threadIdx.x;
    const float* cw = conv_w + (size_t)layer * EDIM * HID;
    float s = 0.f;
    if (k < EDGE_F) {
        for (int j = 0; j < EDIM; j++)
            s = fmaf(__ldg(edge_w + k * EDIM + j), __ldg(cw + (size_t)j * HID + c), s);
    } else {
        for (int j = 0; j < EDIM; j++)
            s = fmaf(__ldg(edge_b + j), __ldg(cw + (size_t)j * HID + c), s);
        s += __ldg(conv_b + (size_t)layer * HID + c);
    }
    wf[((size_t)layer * 7 + k) * HID + c] = s;
}

// ---------------- CSR build (parallel scan) -------------------------------------
__global__ void deg_gsmin_kernel(const int* __restrict__ dst,
                                 const int* __restrict__ batch,
                                 int* __restrict__ deg, int* __restrict__ gstart)
{
    int i = blockIdx.x * blockDim.x + threadIdx.x;
    if (i < NEDGES) atomicAdd(&deg[__ldg(dst + i)], 1);
    if (i < NNODES) atomicMin(&gstart[__ldg(batch + i)], i);
}

__global__ void deg_bsum_kernel(const int* __restrict__ deg, int* __restrict__ bsum)
{
    __shared__ int sh[256];
    int i = blockIdx.x * 256 + threadIdx.x;
    sh[threadIdx.x] = (i < NNODES) ? deg[i] : 0;
    __syncthreads();
    for (int o = 128; o > 0; o >>= 1) {
        if (threadIdx.x < o) sh[threadIdx.x] += sh[threadIdx.x + o];
        __syncthreads();
    }
    if (threadIdx.x == 0) bsum[blockIdx.x] = sh[0];
}

__global__ void bscan_kernel(const int* __restrict__ bsum, int* __restrict__ boffs)
{
    __shared__ int sh[512];
    int t = threadIdx.x;
    int mine = (t < NBLKD) ? bsum[t] : 0;
    sh[t] = mine;
    __syncthreads();
    for (int o = 1; o < 512; o <<= 1) {
        int v = (t >= o) ? sh[t - o] : 0;
        __syncthreads();
        sh[t] += v;
        __syncthreads();
    }
    if (t < NBLKD) boffs[t] = sh[t] - mine;
}

__global__ void rowfill_kernel(const int* __restrict__ deg, const int* __restrict__ boffs,
                               int* __restrict__ rowstart, int* __restrict__ cursor)
{
    __shared__ int sh[256];
    int b = blockIdx.x, t = threadIdx.x;
    int i = b * 256 + t;
    int d = (i < NNODES) ? deg[i] : 0;
    sh[t] = d;
    __syncthreads();
    for (int o = 1; o < 256; o <<= 1) {
        int v = (t >= o) ? sh[t - o] : 0;
        __syncthreads();
        sh[t] += v;
        __syncthreads();
    }
    if (i < NNODES) {
        int rs = boffs[b] + sh[t] - d;
        rowstart[i] = rs;
        cursor[i] = rs;
    }
    if (i == NNODES - 1) rowstart[NNODES] = NEDGES;
}

__global__ void csr_fill_kernel(const int* __restrict__ src,
                                const int* __restrict__ dst,
                                const float* __restrict__ ea,
                                int* __restrict__ cursor,
                                int* __restrict__ csr_src,
                                float* __restrict__ eap)
{
    int e = blockIdx.x * blockDim.x + threadIdx.x;
    if (e >= NEDGES) return;
    int d = __ldg(dst + e);
    int p = atomicAdd(&cursor[d], 1);
    csr_src[p] = __ldg(src + e);
    const float* ep = ea + (size_t)e * EDGE_F;
    float4 a = make_float4(__ldg(ep), __ldg(ep + 1), __ldg(ep + 2), __ldg(ep + 3));
    float2 b = make_float2(__ldg(ep + 4), __ldg(ep + 5));
    *(float4*)(eap + (size_t)p * 8) = a;
    *(float2*)(eap + (size_t)p * 8 + 4) = b;
}

// ---------------- graph ranges --------------------------------------------------
__global__ void gstart_fix_kernel(int* __restrict__ gstart, float* __restrict__ cnt)
{
    __shared__ int sg[NGRAPH + 1];
    int t = threadIdx.x;
    for (int i = t; i <= NGRAPH; i += 1024) sg[i] = gstart[i];
    __syncthreads();
    if (t == 0) {
        sg[NGRAPH] = NNODES;
        for (int g2 = NGRAPH - 1; g2 >= 0; g2--)
            if (sg[g2] > sg[g2 + 1]) sg[g2] = sg[g2 + 1];
    }
    __syncthreads();
    for (int i = t; i <= NGRAPH; i += 1024) gstart[i] = sg[i];
    for (int i = t; i < NGRAPH; i += 1024)
        cnt[i] = fmaxf((float)(sg[i + 1] - sg[i]), 1.0f);
}

// ---------------- GINE gather (permuted ea + src pipeline) ----------------------
__device__ __forceinline__ float4 h4load(const uint2* hp, int idx) {
    uint2 u = __ldg(hp + idx);
    float2 f0 = __half22float2(*(__half2*)&u.x);
    float2 f1 = __half22float2(*(__half2*)&u.y);
    return make_float4(f0.x, f0.y, f1.x, f1.y);
}

__global__ __launch_bounds__(256) void gine_gather_fused(
    const __half* __restrict__ h,
    const float* __restrict__ eap,
    const int* __restrict__ rowstart,
    const int* __restrict__ csr_src,
    const float* __restrict__ wf,
    const float* __restrict__ eps_ptr,
    __half* __restrict__ aeffh,
    float* __restrict__ stats,
    float* __restrict__ gsum,
    float* __restrict__ gsq)
{
    {
        int gid = blockIdx.x * 256 + threadIdx.x;
        if (gid < 262144) {
            gsum[gid] = 0.f; gsum[gid + 262144] = 0.f;
            gsq[gid] = 0.f;  gsq[gid + 262144] = 0.f;
        }
        if (blockIdx.x == 0) {
            stats[threadIdx.x] = 0.f;
            stats[256 + threadIdx.x] = 0.f;
        }
    }

    const int t = threadIdx.x & 63;
    const int group = (blockIdx.x * blockDim.x + threadIdx.x) >> 6;
    const int ngroups = (gridDim.x * blockDim.x) >> 6;
    const float alpha = 1.0f + __ldg(eps_ptr);

    float4 w[EDGE_F];
#pragma unroll
    for (int k = 0; k < EDGE_F; k++)
        w[k] = __ldg((const float4*)(wf + k * HID) + t);
    float4 bf = __ldg((const float4*)(wf + EDGE_F * HID) + t);

    for (int n = group; n < NNODES; n += ngroups) {
        float4 a = h4load((const uint2*)(h + (size_t)n * HID), t);
        a.x *= alpha; a.y *= alpha; a.z *= alpha; a.w *= alpha;

        int lo = __ldg(rowstart + n), hi = __ldg(rowstart + n + 1);
        int s_next = (lo < hi) ? __ldg(csr_src + lo) : 0;
        for (int j = lo; j < hi; j++) {
            int s_cur = s_next;
            if (j + 1 < hi) s_next = __ldg(csr_src + j + 1);
            float4 e03 = __ldg((const float4*)(eap + (size_t)j * 8));
            float2 e45 = __ldg((const float2*)(eap + (size_t)j * 8 + 4));
            float4 hv = h4load((const uint2*)(h + (size_t)s_cur * HID), t);

            float4 ee = bf;
            ee.x = fmaf(e03.x, w[0].x, ee.x); ee.y = fmaf(e03.x, w[0].y, ee.y);
            ee.z = fmaf(e03.x, w[0].z, ee.z); ee.w = fmaf(e03.x, w[0].w, ee.w);
            ee.x = fmaf(e03.y, w[1].x, ee.x); ee.y = fmaf(e03.y, w[1].y, ee.y);
            ee.z = fmaf(e03.y, w[1].z, ee.z); ee.w = fmaf(e03.y, w[1].w, ee.w);
            ee.x = fmaf(e03.z, w[2].x, ee.x); ee.y = fmaf(e03.z, w[2].y, ee.y);
            ee.z = fmaf(e03.z, w[2].z, ee.z); ee.w = fmaf(e03.z, w[2].w, ee.w);
            ee.x = fmaf(e03.w, w[3].x, ee.x); ee.y = fmaf(e03.w, w[3].y, ee.y);
            ee.z = fmaf(e03.w, w[3].z, ee.z); ee.w = fmaf(e03.w, w[3].w, ee.w);
            ee.x = fmaf(e45.x, w[4].x, ee.x); ee.y = fmaf(e45.x, w[4].y, ee.y);
            ee.z = fmaf(e45.x, w[4].z, ee.z); ee.w = fmaf(e45.x, w[4].w, ee.w);
            ee.x = fmaf(e45.y, w[5].x, ee.x); ee.y = fmaf(e45.y, w[5].y, ee.y);
            ee.z = fmaf(e45.y, w[5].z, ee.z); ee.w = fmaf(e45.y, w[5].w, ee.w);

            a.x += fmaxf(hv.x + ee.x, 0.f);
            a.y += fmaxf(hv.y + ee.y, 0.f);
            a.z += fmaxf(hv.z + ee.z, 0.f);
            a.w += fmaxf(hv.w + ee.w, 0.f);
        }
        __half2* ap = (__half2*)(aeffh + (size_t)n * HID);
        ap[2 * t]     = __floats2half2_rn(a.x, a.y);
        ap[2 * t + 1] = __floats2half2_rn(a.z, a.w);
    }
}

// ---------------- merged attention + pooling (block per graph) -----------------
__global__ void pool_att_kernel(const __half* __restrict__ h,
                                const __half* __restrict__ s1,
                                const float* __restrict__ w2,
                                const float* __restrict__ b2,
                                const int* __restrict__ gstart,
                                const float* __restrict__ cnt,
                                float* __restrict__ out)
{
    __shared__ float swexp[128];
    __shared__ float sw2[128];
    __shared__ float swsum;
    int g = blockIdx.x;
    int t = threadIdx.x;
    int warp = t >> 5, lane = t & 31;
    if (t < 128) sw2[t] = __ldg(w2 + t);
    if (t == 0) swsum = 0.f;
    float b2v = __ldg(b2);
    int lo = gstart[g], hi = gstart[g + 1];
    float s = 0.f, mx = 0.f, att = 0.f;
    __syncthreads();

    for (int c0 = lo; c0 < hi; c0 += 128) {
        int nchunk = min(128, hi - c0);
        for (int j = warp; j < nchunk; j += 8) {
            const __half2* sp = (const __half2*)(s1 + (size_t)(c0 + j) * EDIM);
            float acc = 0.f;
#pragma unroll
            for (int k = lane; k < 64; k += 32) {
                float2 f = __half22float2(__ldg(sp + k));
                acc = fmaf(f.x, sw2[2 * k], acc);
                acc = fmaf(f.y, sw2[2 * k + 1], acc);
            }
#pragma unroll
            for (int o = 16; o > 0; o >>= 1) acc += __shfl_down_sync(0xffffffffu, acc, o);
            if (lane == 0) swexp[j] = expf(acc + b2v);
        }
        __syncthreads();
        if (t < 32) {
            float wv = 0.f;
            for (int j = t; j < nchunk; j += 32) wv += swexp[j];
#pragma unroll
            for (int o = 16; o > 0; o >>= 1) wv += __shfl_down_sync(0xffffffffu, wv, o);
            if (t == 0) swsum += wv;
        }
        for (int j = 0; j < nchunk; j++) {
            float v = __half2float(__ldg(h + (size_t)(c0 + j) * HID + t));
            s += v;
            mx = fmaxf(mx, v);
            att = fmaf(v, swexp[j], att);
        }
        __syncthreads();
    }
    float* og = out + (size_t)g * (3 * HID);
    og[t] = s / cnt[g];
    og[HID + t] = mx;
    og[2 * HID + t] = att / (swsum + 1e-8f);
}

// ---------------- host launch --------------------------------------------------------
extern "C" void kernel_launch(void* const* d_in, const int* in_sizes, int n_in,
                              void* d_out, int out_size)
{
    const float* x         = (const float*)d_in[0];
    const float* edge_attr = (const float*)d_in[1];
    const float* node_w    = (const float*)d_in[2];
    const float* node_b    = (const float*)d_in[3];
    const float* edge_w    = (const float*)d_in[4];
    const float* edge_b    = (const float*)d_in[5];
    const float* conv_w    = (const float*)d_in[6];
    const float* conv_b    = (const float*)d_in[7];
    const float* mlp_w1    = (const float*)d_in[8];
    const float* mlp_b1    = (const float*)d_in[9];
    const float* mlp_w2    = (const float*)d_in[10];
    const float* mlp_b2    = (const float*)d_in[11];
    const float* eps       = (const float*)d_in[12];
    const float* bn_gamma  = (const float*)d_in[13];
    const float* bn_beta   = (const float*)d_in[14];
    const float* att_w1    = (const float*)d_in[15];
    const float* att_b1    = (const float*)d_in[16];
    const float* att_w2    = (const float*)d_in[17];
    const float* att_b2    = (const float*)d_in[18];
    const int*   edge_index= (const int*)d_in[19];
    const int*   batch     = (const int*)d_in[20];
    float* out = (float*)d_out;
    (void)bn_beta;   // cancels exactly under PairNorm centering

    const int* src = edge_index;
    const int* dst = edge_index + NEDGES;

    const int HG_SMEM_128 = 2 * HA_TILE_BYTES + 2 * 32 * (128 + 4) * 4;

    cudaFuncSetAttribute(tf32_gemm_h, cudaFuncAttributeMaxDynamicSharedMemorySize, GEMM_SMEM_BYTES);
    cudaFuncSetAttribute(fused_mlp, cudaFuncAttributeMaxDynamicSharedMemorySize, FUSED_SMEM);
    cudaFuncSetAttribute(hgemm_att, cudaFuncAttributeMaxDynamicSharedMemorySize, HG_SMEM_128);

    float *p_stats, *p_gsum, *p_gsq, *p_cnt, *p_wf, *p_eap;
    __half *p_hh0, *p_hh1, *p_zh, *p_aeffh, *p_s1h;
    __half2 *p_w1p, *p_w2p, *p_w1a;
    int *p_deg, *p_bsum, *p_boffs, *p_rowstart, *p_cursor, *p_csrc, *p_gstart;
    cudaGetSymbolAddress((void**)&p_hh0, g_hh0);
    cudaGetSymbolAddress((void**)&p_hh1, g_hh1);
    cudaGetSymbolAddress((void**)&p_zh, g_zh);
    cudaGetSymbolAddress((void**)&p_aeffh, g_aeffh);
    cudaGetSymbolAddress((void**)&p_s1h, g_s1h);
    cudaGetSymbolAddress((void**)&p_w1p, g_w1p);
    cudaGetSymbolAddress((void**)&p_w2p, g_w2p);
    cudaGetSymbolAddress((void**)&p_w1a, g_w1a);
    cudaGetSymbolAddress((void**)&p_eap, g_eap);
    cudaGetSymbolAddress((void**)&p_stats, g_stats);
    cudaGetSymbolAddress((void**)&p_gsum, g_gsum);
    cudaGetSymbolAddress((void**)&p_gsq, g_gsq);
    cudaGetSymbolAddress((void**)&p_cnt, g_cnt);
    cudaGetSymbolAddress((void**)&p_wf, g_wf);
    cudaGetSymbolAddress((void**)&p_deg, g_deg);
    cudaGetSymbolAddress((void**)&p_bsum, g_bsum);
    cudaGetSymbolAddress((void**)&p_boffs, g_boffs);
    cudaGetSymbolAddress((void**)&p_rowstart, g_rowstart);
    cudaGetSymbolAddress((void**)&p_cursor, g_cursor);
    cudaGetSymbolAddress((void**)&p_csrc, g_csr_src);
    cudaGetSymbolAddress((void**)&p_gstart, g_gstart);

    // ----- CSR build (parallel scan) + graph ranges
    cudaMemsetAsync(p_deg, 0, NNODES * sizeof(int));
    cudaMemsetAsync(p_gstart, 0x7F, (NGRAPH + 1) * sizeof(int));
    deg_gsmin_kernel<<<(NEDGES + 255) / 256, 256>>>(dst, batch, p_deg, p_gstart);
    deg_bsum_kernel<<<NBLKD, 256>>>(p_deg, p_bsum);
    bscan_kernel<<<1, 512>>>(p_bsum, p_boffs);
    rowfill_kernel<<<NBLKD, 256>>>(p_deg, p_boffs, p_rowstart, p_cursor);
    csr_fill_kernel<<<(NEDGES + 255) / 256, 256>>>(src, dst, edge_attr, p_cursor, p_csrc, p_eap);
    gstart_fix_kernel<<<1, 1024>>>(p_gstart, p_cnt);

    // ----- weight prep
    wfuse_kernel<<<dim3(NLAYER, 7), HID>>>(edge_w, edge_b, conv_w, conv_b, p_wf);
    wpack_kernel<<<(NLAYER * 128 * 256) / 256, 256>>>(mlp_w1, mlp_w2, p_w1p, p_w2p);
    wpack_att_kernel<<<(128 * 128) / 256, 256>>>(att_w1, p_w1a);

    // ----- node embedding (tf32, half output)
    {
        dim3 grid(HID / 128, (NNODES + 127) / 128);
        tf32_gemm_h<<<grid, 256, GEMM_SMEM_BYTES>>>(NNODES, HID, NODE_F, x, node_w,
                                                    node_b, p_hh0);
    }

    __half* h_cur = p_hh0;
    __half* h_nxt = p_hh1;
    const int mgrid = (NNODES + 127) / 128;

    for (int i = 0; i < NLAYER; i++) {
        gine_gather_fused<<<2048, 256>>>(
            h_cur, p_eap, p_rowstart, p_csrc,
            p_wf + (size_t)i * 7 * HID, eps + i, p_aeffh, p_stats, p_gsum, p_gsq);

        fused_mlp<<<mgrid, 512, FUSED_SMEM>>>(
            NNODES, p_aeffh,
            p_w1p + (size_t)i * 32768, p_w2p + (size_t)i * 32768,
            mlp_b1 + (size_t)i * HID, mlp_b2 + (size_t)i * HID,
            batch, p_gsum, p_gsq, p_stats, p_zh);

        msq_norm_kernel<<<NGRAPH, HID>>>(p_stats, bn_gamma + (size_t)i * HID,
                                         p_cnt, p_gsum, p_gsq, p_gstart, p_zh, h_nxt);

        __half* t = h_cur; h_cur = h_nxt; h_nxt = t;
    }

    // attention hidden: s1 = tanh(h @ att_w1 + att_b1)
    {
        dim3 agrid(1, (NNODES + 127) / 128);
        hgemm_att<<<agrid, 256, HG_SMEM_128>>>(NNODES, h_cur, p_w1a, att_b1, p_s1h);
    }

    // merged attention-score + pooling
    pool_att_kernel<<<NGRAPH, HID>>>(h_cur, p_s1h, att_w2, att_b2, p_gstart, p_cnt, out);

    (void)in_sizes; (void)n_in; (void)out_size;
}